// round 12
// baseline (speedup 1.0000x reference)
#include <cuda_runtime.h>
#include <cuda_bf16.h>

#define DM 2048      // d_model
#define NH 16        // heads
#define DH 128       // d_head
#define DL 512       // d_latent
#define BB 2         // batch
#define SS 2048      // seq
#define ROWS (BB * SS)   // 4096

typedef unsigned long long ull;
typedef unsigned int u32;

// ---- scratch: fp32 intermediates + bf16 hi/lo operand copies ----
__device__ float g_q[ROWS * DM];
__device__ float g_lat[ROWS * DL];
__device__ float g_kv[ROWS * DM];
__device__ float g_att[ROWS * DM];

__device__ __nv_bfloat16 g_xhi[ROWS * DM],  g_xlo[ROWS * DM];
__device__ __nv_bfloat16 g_wqhi[DM * DM],   g_wqlo[DM * DM];
__device__ __nv_bfloat16 g_wkdhi[DM * DL],  g_wkdlo[DM * DL];
__device__ __nv_bfloat16 g_wkuhi[DL * DM],  g_wkulo[DL * DM];
__device__ __nv_bfloat16 g_wohi[DM * DM],   g_wolo[DM * DM];
__device__ __nv_bfloat16 g_lathi[ROWS * DL], g_latlo[ROWS * DL];
__device__ __nv_bfloat16 g_atthi[ROWS * DM], g_attlo[ROWS * DM];
__device__ __nv_bfloat16 g_qhi[ROWS * DM],  g_qlo[ROWS * DM];
__device__ __nv_bfloat16 g_kvhi[ROWS * DM], g_kvlo[ROWS * DM];

// ---- fp32 -> bf16 hi/lo split ----
__device__ __forceinline__ void split4(float4 v, ull& hi, ull& lo) {
    __nv_bfloat16 h0 = __float2bfloat16(v.x), h1 = __float2bfloat16(v.y);
    __nv_bfloat16 h2 = __float2bfloat16(v.z), h3 = __float2bfloat16(v.w);
    __nv_bfloat16 l0 = __float2bfloat16(v.x - __bfloat162float(h0));
    __nv_bfloat16 l1 = __float2bfloat16(v.y - __bfloat162float(h1));
    __nv_bfloat16 l2 = __float2bfloat16(v.z - __bfloat162float(h2));
    __nv_bfloat16 l3 = __float2bfloat16(v.w - __bfloat162float(h3));
    hi = (ull)__bfloat16_as_ushort(h0) | ((ull)__bfloat16_as_ushort(h1) << 16)
       | ((ull)__bfloat16_as_ushort(h2) << 32) | ((ull)__bfloat16_as_ushort(h3) << 48);
    lo = (ull)__bfloat16_as_ushort(l0) | ((ull)__bfloat16_as_ushort(l1) << 16)
       | ((ull)__bfloat16_as_ushort(l2) << 32) | ((ull)__bfloat16_as_ushort(l3) << 48);
}

__global__ __launch_bounds__(256) void splitf(const float4* __restrict__ src,
                                              ull* __restrict__ hi,
                                              ull* __restrict__ lo, int n4) {
    int i = blockIdx.x * 256 + threadIdx.x;
    if (i < n4) {
        ull h, l; split4(src[i], h, l);
        hi[i] = h; lo[i] = l;
    }
}

// ---- warp MMA plumbing ----
__device__ __forceinline__ u32 smem_u32(const void* p) {
    u32 a; asm("{ .reg .u64 t; cvta.to.shared.u64 t, %1; cvt.u32.u64 %0, t; }" : "=r"(a) : "l"(p)); return a;
}
__device__ __forceinline__ void cpa16(u32 dst, const void* src) {
    asm volatile("cp.async.cg.shared.global [%0], [%1], 16;" :: "r"(dst), "l"(src));
}
#define CP_COMMIT() asm volatile("cp.async.commit_group;" ::: "memory")
#define CP_WAIT1()  asm volatile("cp.async.wait_group 1;" ::: "memory")
#define CP_WAIT0()  asm volatile("cp.async.wait_group 0;" ::: "memory")

#define LDSM4(r, addr) \
    asm volatile("ldmatrix.sync.aligned.m8n8.x4.shared.b16 {%0,%1,%2,%3}, [%4];" \
        : "=r"((r)[0]), "=r"((r)[1]), "=r"((r)[2]), "=r"((r)[3]) : "r"(addr))
#define LDSM4T(r, addr) \
    asm volatile("ldmatrix.sync.aligned.m8n8.x4.trans.shared.b16 {%0,%1,%2,%3}, [%4];" \
        : "=r"((r)[0]), "=r"((r)[1]), "=r"((r)[2]), "=r"((r)[3]) : "r"(addr))

__device__ __forceinline__ void mma16(float* c, const u32* a, const u32* b) {
    asm volatile("mma.sync.aligned.m16n8k16.row.col.f32.bf16.bf16.f32 "
        "{%0,%1,%2,%3}, {%4,%5,%6,%7}, {%8,%9}, {%0,%1,%2,%3};"
        : "+f"(c[0]), "+f"(c[1]), "+f"(c[2]), "+f"(c[3])
        : "r"(a[0]), "r"(a[1]), "r"(a[2]), "r"(a[3]), "r"(b[0]), "r"(b[1]));
}

// fast exp on the FMA pipe (no MUFU): 2^(x*log2e), deg-5 Taylor, err ~2e-6
__device__ __forceinline__ float fexp(float x) {
    x = fmaxf(x, -80.f);
    float y = fmaf(x, 1.44269504f, 12582912.f);
    int ni = __float_as_int(y) - __float_as_int(12582912.f);
    float n = y - 12582912.f;
    float f = fmaf(x, 1.44269504f, -n);
    float p = 0.0013333558f;
    p = fmaf(p, f, 0.0096181291f);
    p = fmaf(p, f, 0.055504109f);
    p = fmaf(p, f, 0.24022651f);
    p = fmaf(p, f, 0.69314718f);
    p = fmaf(p, f, 1.0f);
    return p * __int_as_float((ni + 127) << 23);
}

// ---------------------------------------------------------------------------
// bf16-split HMMA GEMM (unchanged from R10).
// ---------------------------------------------------------------------------
#define ABUF 10240
#define BBUF 8704
#define SBUF 37888
__global__ __launch_bounds__(256, 2) void gemm_tc(
        const __nv_bfloat16* __restrict__ Ahi, const __nv_bfloat16* __restrict__ Alo,
        const __nv_bfloat16* __restrict__ Bhi, const __nv_bfloat16* __restrict__ Blo,
        float* __restrict__ C, int M, int N, int K) {
    extern __shared__ __align__(16) char sm[];
    const u32 smb = smem_u32(sm);

    const int tid = threadIdx.x, lane = tid & 31, wid = tid >> 5;
    const int bm = blockIdx.y << 7, bn = blockIdx.x << 7;
    const int wm = (wid >> 2) * 64, wn = (wid & 3) * 32;

    const int sm_m = tid >> 1, sm_kb = (tid & 1) << 4;
    const int sb_k = tid >> 3, sb_n = (tid & 7) << 4;
    const size_t gA = (size_t)(bm + sm_m) * K + sm_kb;
    const size_t gB = (size_t)sb_k * N + bn + sb_n;
    const u32 dA = (u32)(sm_m * 40 + sm_kb) * 2;
    const u32 dB = (u32)(sb_k * 136 + sb_n) * 2;

    const int lrow = (lane & 7) + ((lane >> 3) & 1) * 8;
    const int lcol = (lane >> 4) << 3;
    const u32 a_base = (u32)((wm + lrow) * 40 + lcol) * 2;
    const u32 b_base = (u32)(lrow * 136 + wn + lcol) * 2;

    float acc[4][4][4] = {};
    const int nCh = K >> 5;

    {
        const __nv_bfloat16 *pAh = Ahi + gA, *pAl = Alo + gA;
        const __nv_bfloat16 *pBh = Bhi + gB, *pBl = Blo + gB;
        cpa16(smb + dA, pAh);                  cpa16(smb + dA + 16, pAh + 8);
        cpa16(smb + ABUF + dA, pAl);           cpa16(smb + ABUF + dA + 16, pAl + 8);
        cpa16(smb + 2 * ABUF + dB, pBh);       cpa16(smb + 2 * ABUF + dB + 16, pBh + 8);
        cpa16(smb + 2 * ABUF + BBUF + dB, pBl); cpa16(smb + 2 * ABUF + BBUF + dB + 16, pBl + 8);
        CP_COMMIT();
    }

    for (int c = 0; c < nCh; c++) {
        if (c + 1 < nCh) {
            const u32 o = smb + ((c + 1) & 1) * SBUF;
            const int kc = (c + 1) << 5;
            const __nv_bfloat16 *pAh = Ahi + gA + kc, *pAl = Alo + gA + kc;
            const __nv_bfloat16 *pBh = Bhi + gB + (size_t)kc * N, *pBl = Blo + gB + (size_t)kc * N;
            cpa16(o + dA, pAh);                  cpa16(o + dA + 16, pAh + 8);
            cpa16(o + ABUF + dA, pAl);           cpa16(o + ABUF + dA + 16, pAl + 8);
            cpa16(o + 2 * ABUF + dB, pBh);       cpa16(o + 2 * ABUF + dB + 16, pBh + 8);
            cpa16(o + 2 * ABUF + BBUF + dB, pBl); cpa16(o + 2 * ABUF + BBUF + dB + 16, pBl + 8);
            CP_COMMIT();
            CP_WAIT1();
        } else {
            CP_WAIT0();
        }
        __syncthreads();

        const u32 o = smb + (c & 1) * SBUF;
        const u32 uAh = o, uAl = o + ABUF, uBh = o + 2 * ABUF, uBl = o + 2 * ABUF + BBUF;
#pragma unroll
        for (int ks = 0; ks < 2; ks++) {
            const u32 ka = a_base + ks * 32;
            const u32 kb = b_base + ks * 4352;
            u32 ah[4][4], bh[2][4];
#pragma unroll
            for (int i = 0; i < 4; i++) LDSM4(ah[i], uAh + ka + i * 1280);
#pragma unroll
            for (int j = 0; j < 2; j++) LDSM4T(bh[j], uBh + kb + j * 32);
#pragma unroll
            for (int i = 0; i < 4; i++)
#pragma unroll
                for (int jj = 0; jj < 4; jj++)
                    mma16(acc[i][jj], ah[i], &bh[jj >> 1][(jj & 1) * 2]);
            {
                u32 al[4][4];
#pragma unroll
                for (int i = 0; i < 4; i++) LDSM4(al[i], uAl + ka + i * 1280);
#pragma unroll
                for (int i = 0; i < 4; i++)
#pragma unroll
                    for (int jj = 0; jj < 4; jj++)
                        mma16(acc[i][jj], al[i], &bh[jj >> 1][(jj & 1) * 2]);
            }
            {
                u32 bl[2][4];
#pragma unroll
                for (int j = 0; j < 2; j++) LDSM4T(bl[j], uBl + kb + j * 32);
#pragma unroll
                for (int i = 0; i < 4; i++)
#pragma unroll
                    for (int jj = 0; jj < 4; jj++)
                        mma16(acc[i][jj], ah[i], &bl[jj >> 1][(jj & 1) * 2]);
            }
        }
        __syncthreads();
    }

    const int g = lane >> 2, tg = lane & 3;
#pragma unroll
    for (int i = 0; i < 4; i++)
#pragma unroll
        for (int jj = 0; jj < 4; jj++) {
            const int r0 = bm + wm + i * 16 + g;
            const int c0 = bn + wn + jj * 8 + tg * 2;
            float* p = C + (size_t)r0 * N + c0;
            *(float2*)p = make_float2(acc[i][jj][0], acc[i][jj][1]);
            p += (size_t)8 * N;
            *(float2*)p = make_float2(acc[i][jj][2], acc[i][jj][3]);
        }
}

// ---------------------------------------------------------------------------
// HMMA flash attention. 64 q rows / CTA, KV tiles of 64, 8 warps.
// QK^T and PV both bf16-split 3-term; softmax with poly exp on FMA pipe.
// KV smem tile [kvrow][d] (stride 136) serves both MMAs:
//   QK B-view: [n=kvrow][k=d] via LDSM4  (n8 frags {r0,r2},{r1,r3})
//   PV B-view: [k=kvrow][n=d] via LDSM4T (n8 frags {r0,r1},{r2,r3})
// smem: Qhi/Qlo/Khi/Klo 4x17408 + S 17408 + Phi/Plo 2x9216 + stats 768 = 106240
// ---------------------------------------------------------------------------
#define ATS 136
#define PSTR 72
#define SSTR 68
#define OQH 0
#define OQL 17408
#define OKH 34816
#define OKL 52224
#define OSS 69632
#define OPH 87040
#define OPL 96256
#define OST 105472
#define ATT_SMEM 106240

__global__ __launch_bounds__(256, 2) void mla_attn_tc(
        const __nv_bfloat16* __restrict__ Qhi, const __nv_bfloat16* __restrict__ Qlo,
        const __nv_bfloat16* __restrict__ Khi, const __nv_bfloat16* __restrict__ Klo,
        float* __restrict__ O) {
    extern __shared__ __align__(16) char sm[];
    const u32 smb = smem_u32(sm);
    float* Sf   = (float*)(sm + OSS);
    float* mrow = (float*)(sm + OST);
    float* lrow = (float*)(sm + OST + 256);
    float* arow = (float*)(sm + OST + 512);

    const int tid = threadIdx.x, lane = tid & 31, wid = tid >> 5;
    const int qb = blockIdx.x, h = blockIdx.y, b = blockIdx.z;
    const int wrow = (wid & 3) * 16;   // warp q-row base
    const int wn   = (wid >> 2) * 32;  // QK kv-col base
    const int wd   = (wid >> 2) * 64;  // PV d-col base
    const float scale = 0.08838834764831843f;

    const size_t qoff = ((size_t)b * SS + qb * 64) * DM + h * DH;
    const size_t koff = (size_t)b * SS * DM + h * DH;

    // Q tile (hi/lo) via cp.async
#pragma unroll
    for (int s = 0; s < 4; s++) {
        int id = tid + s * 256;
        int r = id >> 4, c = (id & 15) * 8;
        u32 d = (u32)(r * ATS + c) * 2;
        cpa16(smb + OQH + d, Qhi + qoff + (size_t)r * DM + c);
        cpa16(smb + OQL + d, Qlo + qoff + (size_t)r * DM + c);
    }
    CP_COMMIT();
    if (tid < 64) { mrow[tid] = -3.0e38f; lrow[tid] = 0.f; }

    const int lr = (lane & 7) + ((lane >> 3) & 1) * 8;
    const int lc = (lane >> 4) << 3;
    const int g = lane >> 2, tg = lane & 3;

    float of[8][4] = {};

    for (int t = 0; t < SS / 64; t++) {
        __syncthreads();   // prev PV done before KV overwrite; also covers stats init
        // stage KV tile
#pragma unroll
        for (int s = 0; s < 4; s++) {
            int id = tid + s * 256;
            int r = id >> 4, c = (id & 15) * 8;
            u32 d = (u32)(r * ATS + c) * 2;
            const size_t gsrc = koff + (size_t)(t * 64 + r) * DM + c;
            cpa16(smb + OKH + d, Khi + gsrc);
            cpa16(smb + OKL + d, Klo + gsrc);
        }
        CP_COMMIT();
        CP_WAIT0();
        __syncthreads();

        // ---- S = Q @ K^T (3-term split) ----
        float sv[4][4] = {};
#pragma unroll
        for (int kc = 0; kc < 8; kc++) {
            u32 qa = smb + OQH + (u32)((wrow + lr) * ATS + kc * 16 + lc) * 2;
            u32 ah[4], al[4];
            LDSM4(ah, qa);
            LDSM4(al, qa + (OQL - OQH));
#pragma unroll
            for (int nc = 0; nc < 2; nc++) {
                u32 ka = smb + OKH + (u32)((wn + nc * 16 + lr) * ATS + kc * 16 + lc) * 2;
                u32 bh[4], bl[4];
                LDSM4(bh, ka);
                LDSM4(bl, ka + (OKL - OKH));
                u32 f0h[2] = {bh[0], bh[2]}, f1h[2] = {bh[1], bh[3]};
                u32 f0l[2] = {bl[0], bl[2]}, f1l[2] = {bl[1], bl[3]};
                mma16(sv[nc * 2 + 0], ah, f0h);
                mma16(sv[nc * 2 + 1], ah, f1h);
                mma16(sv[nc * 2 + 0], al, f0h);
                mma16(sv[nc * 2 + 1], al, f1h);
                mma16(sv[nc * 2 + 0], ah, f0l);
                mma16(sv[nc * 2 + 1], ah, f1l);
            }
        }
        // write S -> smem
#pragma unroll
        for (int f = 0; f < 4; f++) {
            int col = wn + f * 8 + tg * 2;
            *(float2*)&Sf[(wrow + g) * SSTR + col]     = make_float2(sv[f][0], sv[f][1]);
            *(float2*)&Sf[(wrow + g + 8) * SSTR + col] = make_float2(sv[f][2], sv[f][3]);
        }
        __syncthreads();

        // ---- online softmax (4 threads/row, poly exp, split P) ----
        {
            int row = tid >> 2, seg = tid & 3;
            const float* sp = &Sf[row * SSTR + seg * 16];
            float x[16];
            float mloc = -3.0e38f;
#pragma unroll
            for (int c = 0; c < 16; c++) { x[c] = sp[c] * scale; mloc = fmaxf(mloc, x[c]); }
            mloc = fmaxf(mloc, __shfl_xor_sync(0xffffffffu, mloc, 1));
            mloc = fmaxf(mloc, __shfl_xor_sync(0xffffffffu, mloc, 2));
            float mold = mrow[row];
            float mnew = fmaxf(mold, mloc);
            float sloc = 0.f;
            u32* php = (u32*)(sm + OPH) + row * (PSTR / 2) + seg * 8;
            u32* plp = (u32*)(sm + OPL) + row * (PSTR / 2) + seg * 8;
#pragma unroll
            for (int c2 = 0; c2 < 8; c2++) {
                float p0 = fexp(x[2 * c2] - mnew);
                float p1 = fexp(x[2 * c2 + 1] - mnew);
                sloc += p0 + p1;
                __nv_bfloat162 hp = __floats2bfloat162_rn(p0, p1);
                float l0 = p0 - __bfloat162float(hp.x);
                float l1 = p1 - __bfloat162float(hp.y);
                __nv_bfloat162 lp = __floats2bfloat162_rn(l0, l1);
                php[c2] = *(u32*)&hp;
                plp[c2] = *(u32*)&lp;
            }
            sloc += __shfl_xor_sync(0xffffffffu, sloc, 1);
            sloc += __shfl_xor_sync(0xffffffffu, sloc, 2);
            if (seg == 0) {
                float al = fexp(mold - mnew);
                arow[row] = al;
                mrow[row] = mnew;
                lrow[row] = lrow[row] * al + sloc;
            }
        }
        __syncthreads();

        // ---- O = alpha*O + P @ V (3-term split) ----
        {
            float a0 = arow[wrow + g], a1 = arow[wrow + g + 8];
#pragma unroll
            for (int f = 0; f < 8; f++) {
                of[f][0] *= a0; of[f][1] *= a0;
                of[f][2] *= a1; of[f][3] *= a1;
            }
        }
#pragma unroll
        for (int kc = 0; kc < 4; kc++) {
            u32 pa = smb + OPH + (u32)((wrow + lr) * PSTR + kc * 16 + lc) * 2;
            u32 ah[4], al[4];
            LDSM4(ah, pa);
            LDSM4(al, pa + (OPL - OPH));
#pragma unroll
            for (int ns = 0; ns < 4; ns++) {
                u32 va = smb + OKH + (u32)((kc * 16 + lr) * ATS + wd + ns * 16 + lc) * 2;
                u32 bh[4], bl[4];
                LDSM4T(bh, va);
                LDSM4T(bl, va + (OKL - OKH));
                mma16(of[ns * 2 + 0], ah, &bh[0]);
                mma16(of[ns * 2 + 1], ah, &bh[2]);
                mma16(of[ns * 2 + 0], al, &bh[0]);
                mma16(of[ns * 2 + 1], al, &bh[2]);
                mma16(of[ns * 2 + 0], ah, &bl[0]);
                mma16(of[ns * 2 + 1], ah, &bl[2]);
            }
        }
    }

    // normalize + store
    float inv0 = 1.f / lrow[wrow + g];
    float inv1 = 1.f / lrow[wrow + g + 8];
    const size_t obase = ((size_t)b * SS + qb * 64 + wrow) * DM + h * DH;
#pragma unroll
    for (int f = 0; f < 8; f++) {
        int col = wd + f * 8 + tg * 2;
        *(float2*)(O + obase + (size_t)g * DM + col) =
            make_float2(of[f][0] * inv0, of[f][1] * inv0);
        *(float2*)(O + obase + (size_t)(g + 8) * DM + col) =
            make_float2(of[f][2] * inv1, of[f][3] * inv1);
    }
}

// ---------------------------------------------------------------------------
static inline void run_split(const float* src, __nv_bfloat16* hi, __nv_bfloat16* lo, int n) {
    int n4 = n >> 2;
    splitf<<<(n4 + 255) / 256, 256>>>((const float4*)src, (ull*)hi, (ull*)lo, n4);
}

extern "C" void kernel_launch(void* const* d_in, const int* in_sizes, int n_in,
                              void* d_out, int out_size) {
    const float* x    = (const float*)d_in[0];
    const float* W_q  = (const float*)d_in[1];
    const float* W_kd = (const float*)d_in[2];
    const float* W_ku = (const float*)d_in[3];
    const float* W_o  = (const float*)d_in[4];
    float* out = (float*)d_out;

    float *pq, *pl, *pkv, *pa;
    cudaGetSymbolAddress((void**)&pq,  g_q);
    cudaGetSymbolAddress((void**)&pl,  g_lat);
    cudaGetSymbolAddress((void**)&pkv, g_kv);
    cudaGetSymbolAddress((void**)&pa,  g_att);

    __nv_bfloat16 *xhi, *xlo, *wqhi, *wqlo, *wkdhi, *wkdlo, *wkuhi, *wkulo;
    __nv_bfloat16 *wohi, *wolo, *lathi, *latlo, *atthi, *attlo;
    __nv_bfloat16 *qhi, *qlo, *kvhi, *kvlo;
    cudaGetSymbolAddress((void**)&xhi,  g_xhi);   cudaGetSymbolAddress((void**)&xlo,  g_xlo);
    cudaGetSymbolAddress((void**)&wqhi, g_wqhi);  cudaGetSymbolAddress((void**)&wqlo, g_wqlo);
    cudaGetSymbolAddress((void**)&wkdhi,g_wkdhi); cudaGetSymbolAddress((void**)&wkdlo,g_wkdlo);
    cudaGetSymbolAddress((void**)&wkuhi,g_wkuhi); cudaGetSymbolAddress((void**)&wkulo,g_wkulo);
    cudaGetSymbolAddress((void**)&wohi, g_wohi);  cudaGetSymbolAddress((void**)&wolo, g_wolo);
    cudaGetSymbolAddress((void**)&lathi,g_lathi); cudaGetSymbolAddress((void**)&latlo,g_latlo);
    cudaGetSymbolAddress((void**)&atthi,g_atthi); cudaGetSymbolAddress((void**)&attlo,g_attlo);
    cudaGetSymbolAddress((void**)&qhi,  g_qhi);   cudaGetSymbolAddress((void**)&qlo,  g_qlo);
    cudaGetSymbolAddress((void**)&kvhi, g_kvhi);  cudaGetSymbolAddress((void**)&kvlo, g_kvlo);

    dim3 blk(256);
    const int gsm = 2 * SBUF;  // 75776
    cudaFuncSetAttribute(gemm_tc, cudaFuncAttributeMaxDynamicSharedMemorySize, gsm);
    cudaFuncSetAttribute(mla_attn_tc, cudaFuncAttributeMaxDynamicSharedMemorySize, ATT_SMEM);

    // split static operands
    run_split(x,    xhi,  xlo,  ROWS * DM);
    run_split(W_q,  wqhi, wqlo, DM * DM);
    run_split(W_kd, wkdhi, wkdlo, DM * DL);
    run_split(W_ku, wkuhi, wkulo, DL * DM);
    run_split(W_o,  wohi, wolo, DM * DM);

    // q = x @ W_q ; split
    gemm_tc<<<dim3(DM / 128, ROWS / 128), blk, gsm>>>(xhi, xlo, wqhi, wqlo, pq, ROWS, DM, DM);
    run_split(pq, qhi, qlo, ROWS * DM);
    // latent = x @ W_kv_down ; split
    gemm_tc<<<dim3(DL / 128, ROWS / 128), blk, gsm>>>(xhi, xlo, wkdhi, wkdlo, pl, ROWS, DL, DM);
    run_split(pl, lathi, latlo, ROWS * DL);
    // kv = latent @ W_kv_up ; split
    gemm_tc<<<dim3(DM / 128, ROWS / 128), blk, gsm>>>(lathi, latlo, wkuhi, wkulo, pkv, ROWS, DM, DL);
    run_split(pkv, kvhi, kvlo, ROWS * DM);

    // fused attention (HMMA)
    mla_attn_tc<<<dim3(SS / 64, NH, BB), blk, ATT_SMEM>>>(qhi, qlo, kvhi, kvlo, pa);

    // out = attn @ W_o
    run_split(pa, atthi, attlo, ROWS * DM);
    gemm_tc<<<dim3(DM / 128, ROWS / 128), blk, gsm>>>(atthi, attlo, wohi, wolo, out, ROWS, DM, DM);
}

// round 13
// speedup vs baseline: 1.0013x; 1.0013x over previous
#include <cuda_runtime.h>
#include <cuda_bf16.h>

#define DM 2048      // d_model
#define NH 16        // heads
#define DH 128       // d_head
#define DL 512       // d_latent
#define BB 2         // batch
#define SS 2048      // seq
#define ROWS (BB * SS)   // 4096

typedef unsigned long long ull;
typedef unsigned int u32;

// ---- scratch: fp32 intermediates + bf16 hi/lo operand copies ----
__device__ float g_q[ROWS * DM];
__device__ float g_lat[ROWS * DL];
__device__ float g_kv[ROWS * DM];
__device__ float g_att[ROWS * DM];

__device__ __nv_bfloat16 g_xhi[ROWS * DM],  g_xlo[ROWS * DM];
__device__ __nv_bfloat16 g_wqhi[DM * DM],   g_wqlo[DM * DM];
__device__ __nv_bfloat16 g_wkdhi[DM * DL],  g_wkdlo[DM * DL];
__device__ __nv_bfloat16 g_wkuhi[DL * DM],  g_wkulo[DL * DM];
__device__ __nv_bfloat16 g_wohi[DM * DM],   g_wolo[DM * DM];
__device__ __nv_bfloat16 g_lathi[ROWS * DL], g_latlo[ROWS * DL];
__device__ __nv_bfloat16 g_atthi[ROWS * DM], g_attlo[ROWS * DM];
__device__ __nv_bfloat16 g_qhi[ROWS * DM],  g_qlo[ROWS * DM];
__device__ __nv_bfloat16 g_kvhi[ROWS * DM], g_kvlo[ROWS * DM];

// ---- fp32 -> bf16 hi/lo split ----
__device__ __forceinline__ void split4(float4 v, ull& hi, ull& lo) {
    __nv_bfloat16 h0 = __float2bfloat16(v.x), h1 = __float2bfloat16(v.y);
    __nv_bfloat16 h2 = __float2bfloat16(v.z), h3 = __float2bfloat16(v.w);
    __nv_bfloat16 l0 = __float2bfloat16(v.x - __bfloat162float(h0));
    __nv_bfloat16 l1 = __float2bfloat16(v.y - __bfloat162float(h1));
    __nv_bfloat16 l2 = __float2bfloat16(v.z - __bfloat162float(h2));
    __nv_bfloat16 l3 = __float2bfloat16(v.w - __bfloat162float(h3));
    hi = (ull)__bfloat16_as_ushort(h0) | ((ull)__bfloat16_as_ushort(h1) << 16)
       | ((ull)__bfloat16_as_ushort(h2) << 32) | ((ull)__bfloat16_as_ushort(h3) << 48);
    lo = (ull)__bfloat16_as_ushort(l0) | ((ull)__bfloat16_as_ushort(l1) << 16)
       | ((ull)__bfloat16_as_ushort(l2) << 32) | ((ull)__bfloat16_as_ushort(l3) << 48);
}

__global__ __launch_bounds__(256) void splitf(const float4* __restrict__ src,
                                              ull* __restrict__ hi,
                                              ull* __restrict__ lo, int n4) {
    int i = blockIdx.x * 256 + threadIdx.x;
    if (i < n4) {
        ull h, l; split4(src[i], h, l);
        hi[i] = h; lo[i] = l;
    }
}

// ---- warp MMA plumbing ----
__device__ __forceinline__ u32 smem_u32(const void* p) {
    u32 a; asm("{ .reg .u64 t; cvta.to.shared.u64 t, %1; cvt.u32.u64 %0, t; }" : "=r"(a) : "l"(p)); return a;
}
__device__ __forceinline__ void cpa16(u32 dst, const void* src) {
    asm volatile("cp.async.cg.shared.global [%0], [%1], 16;" :: "r"(dst), "l"(src));
}
#define CP_COMMIT() asm volatile("cp.async.commit_group;" ::: "memory")
#define CP_WAIT1()  asm volatile("cp.async.wait_group 1;" ::: "memory")
#define CP_WAIT0()  asm volatile("cp.async.wait_group 0;" ::: "memory")

#define LDSM4(r, addr) \
    asm volatile("ldmatrix.sync.aligned.m8n8.x4.shared.b16 {%0,%1,%2,%3}, [%4];" \
        : "=r"((r)[0]), "=r"((r)[1]), "=r"((r)[2]), "=r"((r)[3]) : "r"(addr))
#define LDSM4T(r, addr) \
    asm volatile("ldmatrix.sync.aligned.m8n8.x4.trans.shared.b16 {%0,%1,%2,%3}, [%4];" \
        : "=r"((r)[0]), "=r"((r)[1]), "=r"((r)[2]), "=r"((r)[3]) : "r"(addr))

__device__ __forceinline__ void mma16(float* c, const u32* a, const u32* b) {
    asm volatile("mma.sync.aligned.m16n8k16.row.col.f32.bf16.bf16.f32 "
        "{%0,%1,%2,%3}, {%4,%5,%6,%7}, {%8,%9}, {%0,%1,%2,%3};"
        : "+f"(c[0]), "+f"(c[1]), "+f"(c[2]), "+f"(c[3])
        : "r"(a[0]), "r"(a[1]), "r"(a[2]), "r"(a[3]), "r"(b[0]), "r"(b[1]));
}

// fast exp on the FMA pipe (no MUFU): 2^(x*log2e), deg-5 Taylor, err ~2e-6
__device__ __forceinline__ float fexp(float x) {
    x = fmaxf(x, -80.f);
    float y = fmaf(x, 1.44269504f, 12582912.f);
    int ni = __float_as_int(y) - __float_as_int(12582912.f);
    float n = y - 12582912.f;
    float f = fmaf(x, 1.44269504f, -n);
    float p = 0.0013333558f;
    p = fmaf(p, f, 0.0096181291f);
    p = fmaf(p, f, 0.055504109f);
    p = fmaf(p, f, 0.24022651f);
    p = fmaf(p, f, 0.69314718f);
    p = fmaf(p, f, 1.0f);
    return p * __int_as_float((ni + 127) << 23);
}

// ---------------------------------------------------------------------------
// bf16-split HMMA GEMM (unchanged from R10).
// ---------------------------------------------------------------------------
#define ABUF 10240
#define BBUF 8704
#define SBUF 37888
__global__ __launch_bounds__(256, 2) void gemm_tc(
        const __nv_bfloat16* __restrict__ Ahi, const __nv_bfloat16* __restrict__ Alo,
        const __nv_bfloat16* __restrict__ Bhi, const __nv_bfloat16* __restrict__ Blo,
        float* __restrict__ C, int M, int N, int K) {
    extern __shared__ __align__(16) char sm[];
    const u32 smb = smem_u32(sm);

    const int tid = threadIdx.x, lane = tid & 31, wid = tid >> 5;
    const int bm = blockIdx.y << 7, bn = blockIdx.x << 7;
    const int wm = (wid >> 2) * 64, wn = (wid & 3) * 32;

    const int sm_m = tid >> 1, sm_kb = (tid & 1) << 4;
    const int sb_k = tid >> 3, sb_n = (tid & 7) << 4;
    const size_t gA = (size_t)(bm + sm_m) * K + sm_kb;
    const size_t gB = (size_t)sb_k * N + bn + sb_n;
    const u32 dA = (u32)(sm_m * 40 + sm_kb) * 2;
    const u32 dB = (u32)(sb_k * 136 + sb_n) * 2;

    const int lrow = (lane & 7) + ((lane >> 3) & 1) * 8;
    const int lcol = (lane >> 4) << 3;
    const u32 a_base = (u32)((wm + lrow) * 40 + lcol) * 2;
    const u32 b_base = (u32)(lrow * 136 + wn + lcol) * 2;

    float acc[4][4][4] = {};
    const int nCh = K >> 5;

    {
        const __nv_bfloat16 *pAh = Ahi + gA, *pAl = Alo + gA;
        const __nv_bfloat16 *pBh = Bhi + gB, *pBl = Blo + gB;
        cpa16(smb + dA, pAh);                  cpa16(smb + dA + 16, pAh + 8);
        cpa16(smb + ABUF + dA, pAl);           cpa16(smb + ABUF + dA + 16, pAl + 8);
        cpa16(smb + 2 * ABUF + dB, pBh);       cpa16(smb + 2 * ABUF + dB + 16, pBh + 8);
        cpa16(smb + 2 * ABUF + BBUF + dB, pBl); cpa16(smb + 2 * ABUF + BBUF + dB + 16, pBl + 8);
        CP_COMMIT();
    }

    for (int c = 0; c < nCh; c++) {
        if (c + 1 < nCh) {
            const u32 o = smb + ((c + 1) & 1) * SBUF;
            const int kc = (c + 1) << 5;
            const __nv_bfloat16 *pAh = Ahi + gA + kc, *pAl = Alo + gA + kc;
            const __nv_bfloat16 *pBh = Bhi + gB + (size_t)kc * N, *pBl = Blo + gB + (size_t)kc * N;
            cpa16(o + dA, pAh);                  cpa16(o + dA + 16, pAh + 8);
            cpa16(o + ABUF + dA, pAl);           cpa16(o + ABUF + dA + 16, pAl + 8);
            cpa16(o + 2 * ABUF + dB, pBh);       cpa16(o + 2 * ABUF + dB + 16, pBh + 8);
            cpa16(o + 2 * ABUF + BBUF + dB, pBl); cpa16(o + 2 * ABUF + BBUF + dB + 16, pBl + 8);
            CP_COMMIT();
            CP_WAIT1();
        } else {
            CP_WAIT0();
        }
        __syncthreads();

        const u32 o = smb + (c & 1) * SBUF;
        const u32 uAh = o, uAl = o + ABUF, uBh = o + 2 * ABUF, uBl = o + 2 * ABUF + BBUF;
#pragma unroll
        for (int ks = 0; ks < 2; ks++) {
            const u32 ka = a_base + ks * 32;
            const u32 kb = b_base + ks * 4352;
            u32 ah[4][4], bh[2][4];
#pragma unroll
            for (int i = 0; i < 4; i++) LDSM4(ah[i], uAh + ka + i * 1280);
#pragma unroll
            for (int j = 0; j < 2; j++) LDSM4T(bh[j], uBh + kb + j * 32);
#pragma unroll
            for (int i = 0; i < 4; i++)
#pragma unroll
                for (int jj = 0; jj < 4; jj++)
                    mma16(acc[i][jj], ah[i], &bh[jj >> 1][(jj & 1) * 2]);
            {
                u32 al[4][4];
#pragma unroll
                for (int i = 0; i < 4; i++) LDSM4(al[i], uAl + ka + i * 1280);
#pragma unroll
                for (int i = 0; i < 4; i++)
#pragma unroll
                    for (int jj = 0; jj < 4; jj++)
                        mma16(acc[i][jj], al[i], &bh[jj >> 1][(jj & 1) * 2]);
            }
            {
                u32 bl[2][4];
#pragma unroll
                for (int j = 0; j < 2; j++) LDSM4T(bl[j], uBl + kb + j * 32);
#pragma unroll
                for (int i = 0; i < 4; i++)
#pragma unroll
                    for (int jj = 0; jj < 4; jj++)
                        mma16(acc[i][jj], ah[i], &bl[jj >> 1][(jj & 1) * 2]);
            }
        }
        __syncthreads();
    }

    const int g = lane >> 2, tg = lane & 3;
#pragma unroll
    for (int i = 0; i < 4; i++)
#pragma unroll
        for (int jj = 0; jj < 4; jj++) {
            const int r0 = bm + wm + i * 16 + g;
            const int c0 = bn + wn + jj * 8 + tg * 2;
            float* p = C + (size_t)r0 * N + c0;
            *(float2*)p = make_float2(acc[i][jj][0], acc[i][jj][1]);
            p += (size_t)8 * N;
            *(float2*)p = make_float2(acc[i][jj][2], acc[i][jj][3]);
        }
}

// ---------------------------------------------------------------------------
// HMMA flash attention. 64 q rows / CTA, KV tiles of 64, 8 warps.
// QK^T and PV both bf16-split 3-term; softmax with poly exp on FMA pipe.
// KV smem tile [kvrow][d] (stride 136) serves both MMAs:
//   QK B-view: [n=kvrow][k=d] via LDSM4  (n8 frags {r0,r2},{r1,r3})
//   PV B-view: [k=kvrow][n=d] via LDSM4T (n8 frags {r0,r1},{r2,r3})
// smem: Qhi/Qlo/Khi/Klo 4x17408 + S 17408 + Phi/Plo 2x9216 + stats 768 = 106240
// ---------------------------------------------------------------------------
#define ATS 136
#define PSTR 72
#define SSTR 68
#define OQH 0
#define OQL 17408
#define OKH 34816
#define OKL 52224
#define OSS 69632
#define OPH 87040
#define OPL 96256
#define OST 105472
#define ATT_SMEM 106240

__global__ __launch_bounds__(256, 2) void mla_attn_tc(
        const __nv_bfloat16* __restrict__ Qhi, const __nv_bfloat16* __restrict__ Qlo,
        const __nv_bfloat16* __restrict__ Khi, const __nv_bfloat16* __restrict__ Klo,
        float* __restrict__ O) {
    extern __shared__ __align__(16) char sm[];
    const u32 smb = smem_u32(sm);
    float* Sf   = (float*)(sm + OSS);
    float* mrow = (float*)(sm + OST);
    float* lrow = (float*)(sm + OST + 256);
    float* arow = (float*)(sm + OST + 512);

    const int tid = threadIdx.x, lane = tid & 31, wid = tid >> 5;
    const int qb = blockIdx.x, h = blockIdx.y, b = blockIdx.z;
    const int wrow = (wid & 3) * 16;   // warp q-row base
    const int wn   = (wid >> 2) * 32;  // QK kv-col base
    const int wd   = (wid >> 2) * 64;  // PV d-col base
    const float scale = 0.08838834764831843f;

    const size_t qoff = ((size_t)b * SS + qb * 64) * DM + h * DH;
    const size_t koff = (size_t)b * SS * DM + h * DH;

    // Q tile (hi/lo) via cp.async
#pragma unroll
    for (int s = 0; s < 4; s++) {
        int id = tid + s * 256;
        int r = id >> 4, c = (id & 15) * 8;
        u32 d = (u32)(r * ATS + c) * 2;
        cpa16(smb + OQH + d, Qhi + qoff + (size_t)r * DM + c);
        cpa16(smb + OQL + d, Qlo + qoff + (size_t)r * DM + c);
    }
    CP_COMMIT();
    if (tid < 64) { mrow[tid] = -3.0e38f; lrow[tid] = 0.f; }

    const int lr = (lane & 7) + ((lane >> 3) & 1) * 8;
    const int lc = (lane >> 4) << 3;
    const int g = lane >> 2, tg = lane & 3;

    float of[8][4] = {};

    for (int t = 0; t < SS / 64; t++) {
        __syncthreads();   // prev PV done before KV overwrite; also covers stats init
        // stage KV tile
#pragma unroll
        for (int s = 0; s < 4; s++) {
            int id = tid + s * 256;
            int r = id >> 4, c = (id & 15) * 8;
            u32 d = (u32)(r * ATS + c) * 2;
            const size_t gsrc = koff + (size_t)(t * 64 + r) * DM + c;
            cpa16(smb + OKH + d, Khi + gsrc);
            cpa16(smb + OKL + d, Klo + gsrc);
        }
        CP_COMMIT();
        CP_WAIT0();
        __syncthreads();

        // ---- S = Q @ K^T (3-term split) ----
        float sv[4][4] = {};
#pragma unroll
        for (int kc = 0; kc < 8; kc++) {
            u32 qa = smb + OQH + (u32)((wrow + lr) * ATS + kc * 16 + lc) * 2;
            u32 ah[4], al[4];
            LDSM4(ah, qa);
            LDSM4(al, qa + (OQL - OQH));
#pragma unroll
            for (int nc = 0; nc < 2; nc++) {
                u32 ka = smb + OKH + (u32)((wn + nc * 16 + lr) * ATS + kc * 16 + lc) * 2;
                u32 bh[4], bl[4];
                LDSM4(bh, ka);
                LDSM4(bl, ka + (OKL - OKH));
                u32 f0h[2] = {bh[0], bh[2]}, f1h[2] = {bh[1], bh[3]};
                u32 f0l[2] = {bl[0], bl[2]}, f1l[2] = {bl[1], bl[3]};
                mma16(sv[nc * 2 + 0], ah, f0h);
                mma16(sv[nc * 2 + 1], ah, f1h);
                mma16(sv[nc * 2 + 0], al, f0h);
                mma16(sv[nc * 2 + 1], al, f1h);
                mma16(sv[nc * 2 + 0], ah, f0l);
                mma16(sv[nc * 2 + 1], ah, f1l);
            }
        }
        // write S -> smem
#pragma unroll
        for (int f = 0; f < 4; f++) {
            int col = wn + f * 8 + tg * 2;
            *(float2*)&Sf[(wrow + g) * SSTR + col]     = make_float2(sv[f][0], sv[f][1]);
            *(float2*)&Sf[(wrow + g + 8) * SSTR + col] = make_float2(sv[f][2], sv[f][3]);
        }
        __syncthreads();

        // ---- online softmax (4 threads/row, poly exp, split P) ----
        {
            int row = tid >> 2, seg = tid & 3;
            const float* sp = &Sf[row * SSTR + seg * 16];
            float x[16];
            float mloc = -3.0e38f;
#pragma unroll
            for (int c = 0; c < 16; c++) { x[c] = sp[c] * scale; mloc = fmaxf(mloc, x[c]); }
            mloc = fmaxf(mloc, __shfl_xor_sync(0xffffffffu, mloc, 1));
            mloc = fmaxf(mloc, __shfl_xor_sync(0xffffffffu, mloc, 2));
            float mold = mrow[row];
            float mnew = fmaxf(mold, mloc);
            float sloc = 0.f;
            u32* php = (u32*)(sm + OPH) + row * (PSTR / 2) + seg * 8;
            u32* plp = (u32*)(sm + OPL) + row * (PSTR / 2) + seg * 8;
#pragma unroll
            for (int c2 = 0; c2 < 8; c2++) {
                float p0 = fexp(x[2 * c2] - mnew);
                float p1 = fexp(x[2 * c2 + 1] - mnew);
                sloc += p0 + p1;
                __nv_bfloat162 hp = __floats2bfloat162_rn(p0, p1);
                float l0 = p0 - __bfloat162float(hp.x);
                float l1 = p1 - __bfloat162float(hp.y);
                __nv_bfloat162 lp = __floats2bfloat162_rn(l0, l1);
                php[c2] = *(u32*)&hp;
                plp[c2] = *(u32*)&lp;
            }
            sloc += __shfl_xor_sync(0xffffffffu, sloc, 1);
            sloc += __shfl_xor_sync(0xffffffffu, sloc, 2);
            if (seg == 0) {
                float al = fexp(mold - mnew);
                arow[row] = al;
                mrow[row] = mnew;
                lrow[row] = lrow[row] * al + sloc;
            }
        }
        __syncthreads();

        // ---- O = alpha*O + P @ V (3-term split) ----
        {
            float a0 = arow[wrow + g], a1 = arow[wrow + g + 8];
#pragma unroll
            for (int f = 0; f < 8; f++) {
                of[f][0] *= a0; of[f][1] *= a0;
                of[f][2] *= a1; of[f][3] *= a1;
            }
        }
#pragma unroll
        for (int kc = 0; kc < 4; kc++) {
            u32 pa = smb + OPH + (u32)((wrow + lr) * PSTR + kc * 16 + lc) * 2;
            u32 ah[4], al[4];
            LDSM4(ah, pa);
            LDSM4(al, pa + (OPL - OPH));
#pragma unroll
            for (int ns = 0; ns < 4; ns++) {
                u32 va = smb + OKH + (u32)((kc * 16 + lr) * ATS + wd + ns * 16 + lc) * 2;
                u32 bh[4], bl[4];
                LDSM4T(bh, va);
                LDSM4T(bl, va + (OKL - OKH));
                mma16(of[ns * 2 + 0], ah, &bh[0]);
                mma16(of[ns * 2 + 1], ah, &bh[2]);
                mma16(of[ns * 2 + 0], al, &bh[0]);
                mma16(of[ns * 2 + 1], al, &bh[2]);
                mma16(of[ns * 2 + 0], ah, &bl[0]);
                mma16(of[ns * 2 + 1], ah, &bl[2]);
            }
        }
    }

    // normalize + store
    float inv0 = 1.f / lrow[wrow + g];
    float inv1 = 1.f / lrow[wrow + g + 8];
    const size_t obase = ((size_t)b * SS + qb * 64 + wrow) * DM + h * DH;
#pragma unroll
    for (int f = 0; f < 8; f++) {
        int col = wd + f * 8 + tg * 2;
        *(float2*)(O + obase + (size_t)g * DM + col) =
            make_float2(of[f][0] * inv0, of[f][1] * inv0);
        *(float2*)(O + obase + (size_t)(g + 8) * DM + col) =
            make_float2(of[f][2] * inv1, of[f][3] * inv1);
    }
}

// ---------------------------------------------------------------------------
static inline void run_split(const float* src, __nv_bfloat16* hi, __nv_bfloat16* lo, int n) {
    int n4 = n >> 2;
    splitf<<<(n4 + 255) / 256, 256>>>((const float4*)src, (ull*)hi, (ull*)lo, n4);
}

extern "C" void kernel_launch(void* const* d_in, const int* in_sizes, int n_in,
                              void* d_out, int out_size) {
    const float* x    = (const float*)d_in[0];
    const float* W_q  = (const float*)d_in[1];
    const float* W_kd = (const float*)d_in[2];
    const float* W_ku = (const float*)d_in[3];
    const float* W_o  = (const float*)d_in[4];
    float* out = (float*)d_out;

    float *pq, *pl, *pkv, *pa;
    cudaGetSymbolAddress((void**)&pq,  g_q);
    cudaGetSymbolAddress((void**)&pl,  g_lat);
    cudaGetSymbolAddress((void**)&pkv, g_kv);
    cudaGetSymbolAddress((void**)&pa,  g_att);

    __nv_bfloat16 *xhi, *xlo, *wqhi, *wqlo, *wkdhi, *wkdlo, *wkuhi, *wkulo;
    __nv_bfloat16 *wohi, *wolo, *lathi, *latlo, *atthi, *attlo;
    __nv_bfloat16 *qhi, *qlo, *kvhi, *kvlo;
    cudaGetSymbolAddress((void**)&xhi,  g_xhi);   cudaGetSymbolAddress((void**)&xlo,  g_xlo);
    cudaGetSymbolAddress((void**)&wqhi, g_wqhi);  cudaGetSymbolAddress((void**)&wqlo, g_wqlo);
    cudaGetSymbolAddress((void**)&wkdhi,g_wkdhi); cudaGetSymbolAddress((void**)&wkdlo,g_wkdlo);
    cudaGetSymbolAddress((void**)&wkuhi,g_wkuhi); cudaGetSymbolAddress((void**)&wkulo,g_wkulo);
    cudaGetSymbolAddress((void**)&wohi, g_wohi);  cudaGetSymbolAddress((void**)&wolo, g_wolo);
    cudaGetSymbolAddress((void**)&lathi,g_lathi); cudaGetSymbolAddress((void**)&latlo,g_latlo);
    cudaGetSymbolAddress((void**)&atthi,g_atthi); cudaGetSymbolAddress((void**)&attlo,g_attlo);
    cudaGetSymbolAddress((void**)&qhi,  g_qhi);   cudaGetSymbolAddress((void**)&qlo,  g_qlo);
    cudaGetSymbolAddress((void**)&kvhi, g_kvhi);  cudaGetSymbolAddress((void**)&kvlo, g_kvlo);

    dim3 blk(256);
    const int gsm = 2 * SBUF;  // 75776
    cudaFuncSetAttribute(gemm_tc, cudaFuncAttributeMaxDynamicSharedMemorySize, gsm);
    cudaFuncSetAttribute(mla_attn_tc, cudaFuncAttributeMaxDynamicSharedMemorySize, ATT_SMEM);

    // split static operands
    run_split(x,    xhi,  xlo,  ROWS * DM);
    run_split(W_q,  wqhi, wqlo, DM * DM);
    run_split(W_kd, wkdhi, wkdlo, DM * DL);
    run_split(W_ku, wkuhi, wkulo, DL * DM);
    run_split(W_o,  wohi, wolo, DM * DM);

    // q = x @ W_q ; split
    gemm_tc<<<dim3(DM / 128, ROWS / 128), blk, gsm>>>(xhi, xlo, wqhi, wqlo, pq, ROWS, DM, DM);
    run_split(pq, qhi, qlo, ROWS * DM);
    // latent = x @ W_kv_down ; split
    gemm_tc<<<dim3(DL / 128, ROWS / 128), blk, gsm>>>(xhi, xlo, wkdhi, wkdlo, pl, ROWS, DL, DM);
    run_split(pl, lathi, latlo, ROWS * DL);
    // kv = latent @ W_kv_up ; split
    gemm_tc<<<dim3(DM / 128, ROWS / 128), blk, gsm>>>(lathi, latlo, wkuhi, wkulo, pkv, ROWS, DM, DL);
    run_split(pkv, kvhi, kvlo, ROWS * DM);

    // fused attention (HMMA)
    mla_attn_tc<<<dim3(SS / 64, NH, BB), blk, ATT_SMEM>>>(qhi, qlo, kvhi, kvlo, pa);

    // out = attn @ W_o
    run_split(pa, atthi, attlo, ROWS * DM);
    gemm_tc<<<dim3(DM / 128, ROWS / 128), blk, gsm>>>(atthi, attlo, wohi, wolo, out, ROWS, DM, DM);
}

// round 14
// speedup vs baseline: 1.0054x; 1.0041x over previous
#include <cuda_runtime.h>
#include <cuda_bf16.h>

#define DM 2048      // d_model
#define NH 16        // heads
#define DH 128       // d_head
#define DL 512       // d_latent
#define BB 2         // batch
#define SS 2048      // seq
#define ROWS (BB * SS)   // 4096

typedef unsigned long long ull;
typedef unsigned int u32;

// ---- scratch: bf16 hi/lo operand copies only (no fp32 intermediates) ----
__device__ __nv_bfloat16 g_xhi[ROWS * DM],  g_xlo[ROWS * DM];
__device__ __nv_bfloat16 g_wqhi[DM * DM],   g_wqlo[DM * DM];
__device__ __nv_bfloat16 g_wkdhi[DM * DL],  g_wkdlo[DM * DL];
__device__ __nv_bfloat16 g_wkuhi[DL * DM],  g_wkulo[DL * DM];
__device__ __nv_bfloat16 g_wohi[DM * DM],   g_wolo[DM * DM];
__device__ __nv_bfloat16 g_lathi[ROWS * DL], g_latlo[ROWS * DL];
__device__ __nv_bfloat16 g_atthi[ROWS * DM], g_attlo[ROWS * DM];
__device__ __nv_bfloat16 g_qhi[ROWS * DM],  g_qlo[ROWS * DM];
__device__ __nv_bfloat16 g_kvhi[ROWS * DM], g_kvlo[ROWS * DM];

// ---- fp32 -> bf16 hi/lo split helpers ----
__device__ __forceinline__ void split4(float4 v, ull& hi, ull& lo) {
    __nv_bfloat16 h0 = __float2bfloat16(v.x), h1 = __float2bfloat16(v.y);
    __nv_bfloat16 h2 = __float2bfloat16(v.z), h3 = __float2bfloat16(v.w);
    __nv_bfloat16 l0 = __float2bfloat16(v.x - __bfloat162float(h0));
    __nv_bfloat16 l1 = __float2bfloat16(v.y - __bfloat162float(h1));
    __nv_bfloat16 l2 = __float2bfloat16(v.z - __bfloat162float(h2));
    __nv_bfloat16 l3 = __float2bfloat16(v.w - __bfloat162float(h3));
    hi = (ull)__bfloat16_as_ushort(h0) | ((ull)__bfloat16_as_ushort(h1) << 16)
       | ((ull)__bfloat16_as_ushort(h2) << 32) | ((ull)__bfloat16_as_ushort(h3) << 48);
    lo = (ull)__bfloat16_as_ushort(l0) | ((ull)__bfloat16_as_ushort(l1) << 16)
       | ((ull)__bfloat16_as_ushort(l2) << 32) | ((ull)__bfloat16_as_ushort(l3) << 48);
}

__device__ __forceinline__ u32 split2(float x, float y, u32& lo) {
    __nv_bfloat162 h = __floats2bfloat162_rn(x, y);
    float lx = x - __bfloat162float(h.x), ly = y - __bfloat162float(h.y);
    __nv_bfloat162 l = __floats2bfloat162_rn(lx, ly);
    lo = *(u32*)&l;
    return *(u32*)&h;
}

__global__ __launch_bounds__(256) void splitf(const float4* __restrict__ src,
                                              ull* __restrict__ hi,
                                              ull* __restrict__ lo, int n4) {
    int i = blockIdx.x * 256 + threadIdx.x;
    if (i < n4) {
        ull h, l; split4(src[i], h, l);
        hi[i] = h; lo[i] = l;
    }
}

// ---- warp MMA plumbing ----
__device__ __forceinline__ u32 smem_u32(const void* p) {
    u32 a; asm("{ .reg .u64 t; cvta.to.shared.u64 t, %1; cvt.u32.u64 %0, t; }" : "=r"(a) : "l"(p)); return a;
}
__device__ __forceinline__ void cpa16(u32 dst, const void* src) {
    asm volatile("cp.async.cg.shared.global [%0], [%1], 16;" :: "r"(dst), "l"(src));
}
#define CP_COMMIT() asm volatile("cp.async.commit_group;" ::: "memory")
#define CP_WAIT1()  asm volatile("cp.async.wait_group 1;" ::: "memory")
#define CP_WAIT0()  asm volatile("cp.async.wait_group 0;" ::: "memory")

#define LDSM4(r, addr) \
    asm volatile("ldmatrix.sync.aligned.m8n8.x4.shared.b16 {%0,%1,%2,%3}, [%4];" \
        : "=r"((r)[0]), "=r"((r)[1]), "=r"((r)[2]), "=r"((r)[3]) : "r"(addr))
#define LDSM4T(r, addr) \
    asm volatile("ldmatrix.sync.aligned.m8n8.x4.trans.shared.b16 {%0,%1,%2,%3}, [%4];" \
        : "=r"((r)[0]), "=r"((r)[1]), "=r"((r)[2]), "=r"((r)[3]) : "r"(addr))

__device__ __forceinline__ void mma16(float* c, const u32* a, const u32* b) {
    asm volatile("mma.sync.aligned.m16n8k16.row.col.f32.bf16.bf16.f32 "
        "{%0,%1,%2,%3}, {%4,%5,%6,%7}, {%8,%9}, {%0,%1,%2,%3};"
        : "+f"(c[0]), "+f"(c[1]), "+f"(c[2]), "+f"(c[3])
        : "r"(a[0]), "r"(a[1]), "r"(a[2]), "r"(a[3]), "r"(b[0]), "r"(b[1]));
}

// fast exp on the FMA pipe (no MUFU): 2^(x*log2e), deg-5 Taylor, err ~2e-6
__device__ __forceinline__ float fexp(float x) {
    x = fmaxf(x, -80.f);
    float y = fmaf(x, 1.44269504f, 12582912.f);
    int ni = __float_as_int(y) - __float_as_int(12582912.f);
    float n = y - 12582912.f;
    float f = fmaf(x, 1.44269504f, -n);
    float p = 0.0013333558f;
    p = fmaf(p, f, 0.0096181291f);
    p = fmaf(p, f, 0.055504109f);
    p = fmaf(p, f, 0.24022651f);
    p = fmaf(p, f, 0.69314718f);
    p = fmaf(p, f, 1.0f);
    return p * __int_as_float((ni + 127) << 23);
}

// ---------------------------------------------------------------------------
// Shared GEMM mainloop (bf16-split 3-term HMMA), two epilogues:
//   gemm_tc   : fp32 C output (final projection)
//   gemm_tc_s : split bf16 hi/lo output (+ optional scale folded in)
// ---------------------------------------------------------------------------
#define ABUF 10240
#define BBUF 8704
#define SBUF 37888

#define GEMM_MAINLOOP()                                                                     \
    extern __shared__ __align__(16) char sm[];                                              \
    const u32 smb = smem_u32(sm);                                                           \
    const int tid = threadIdx.x, lane = tid & 31, wid = tid >> 5;                           \
    const int bm = blockIdx.y << 7, bn = blockIdx.x << 7;                                   \
    const int wm = (wid >> 2) * 64, wn = (wid & 3) * 32;                                    \
    const int sm_m = tid >> 1, sm_kb = (tid & 1) << 4;                                      \
    const int sb_k = tid >> 3, sb_n = (tid & 7) << 4;                                       \
    const size_t gA = (size_t)(bm + sm_m) * K + sm_kb;                                      \
    const size_t gB = (size_t)sb_k * N + bn + sb_n;                                         \
    const u32 dA = (u32)(sm_m * 40 + sm_kb) * 2;                                            \
    const u32 dB = (u32)(sb_k * 136 + sb_n) * 2;                                            \
    const int lrow = (lane & 7) + ((lane >> 3) & 1) * 8;                                    \
    const int lcol = (lane >> 4) << 3;                                                      \
    const u32 a_base = (u32)((wm + lrow) * 40 + lcol) * 2;                                  \
    const u32 b_base = (u32)(lrow * 136 + wn + lcol) * 2;                                   \
    float acc[4][4][4] = {};                                                                \
    const int nCh = K >> 5;                                                                 \
    {                                                                                       \
        const __nv_bfloat16 *pAh = Ahi + gA, *pAl = Alo + gA;                               \
        const __nv_bfloat16 *pBh = Bhi + gB, *pBl = Blo + gB;                               \
        cpa16(smb + dA, pAh);                   cpa16(smb + dA + 16, pAh + 8);              \
        cpa16(smb + ABUF + dA, pAl);            cpa16(smb + ABUF + dA + 16, pAl + 8);       \
        cpa16(smb + 2 * ABUF + dB, pBh);        cpa16(smb + 2 * ABUF + dB + 16, pBh + 8);   \
        cpa16(smb + 2 * ABUF + BBUF + dB, pBl); cpa16(smb + 2 * ABUF + BBUF + dB + 16, pBl + 8); \
        CP_COMMIT();                                                                        \
    }                                                                                       \
    for (int c = 0; c < nCh; c++) {                                                         \
        if (c + 1 < nCh) {                                                                  \
            const u32 o = smb + ((c + 1) & 1) * SBUF;                                       \
            const int kc = (c + 1) << 5;                                                    \
            const __nv_bfloat16 *pAh = Ahi + gA + kc, *pAl = Alo + gA + kc;                 \
            const __nv_bfloat16 *pBh = Bhi + gB + (size_t)kc * N, *pBl = Blo + gB + (size_t)kc * N; \
            cpa16(o + dA, pAh);                   cpa16(o + dA + 16, pAh + 8);              \
            cpa16(o + ABUF + dA, pAl);            cpa16(o + ABUF + dA + 16, pAl + 8);       \
            cpa16(o + 2 * ABUF + dB, pBh);        cpa16(o + 2 * ABUF + dB + 16, pBh + 8);   \
            cpa16(o + 2 * ABUF + BBUF + dB, pBl); cpa16(o + 2 * ABUF + BBUF + dB + 16, pBl + 8); \
            CP_COMMIT();                                                                    \
            CP_WAIT1();                                                                     \
        } else {                                                                            \
            CP_WAIT0();                                                                     \
        }                                                                                   \
        __syncthreads();                                                                    \
        const u32 o = smb + (c & 1) * SBUF;                                                 \
        const u32 uAh = o, uAl = o + ABUF, uBh = o + 2 * ABUF, uBl = o + 2 * ABUF + BBUF;   \
        _Pragma("unroll")                                                                   \
        for (int ks = 0; ks < 2; ks++) {                                                    \
            const u32 ka = a_base + ks * 32;                                                \
            const u32 kb = b_base + ks * 4352;                                              \
            u32 ah[4][4], bh[2][4];                                                         \
            _Pragma("unroll")                                                               \
            for (int i = 0; i < 4; i++) LDSM4(ah[i], uAh + ka + i * 1280);                  \
            _Pragma("unroll")                                                               \
            for (int j = 0; j < 2; j++) LDSM4T(bh[j], uBh + kb + j * 32);                   \
            _Pragma("unroll")                                                               \
            for (int i = 0; i < 4; i++)                                                     \
                _Pragma("unroll")                                                           \
                for (int jj = 0; jj < 4; jj++)                                              \
                    mma16(acc[i][jj], ah[i], &bh[jj >> 1][(jj & 1) * 2]);                   \
            {                                                                               \
                u32 al[4][4];                                                               \
                _Pragma("unroll")                                                           \
                for (int i = 0; i < 4; i++) LDSM4(al[i], uAl + ka + i * 1280);              \
                _Pragma("unroll")                                                           \
                for (int i = 0; i < 4; i++)                                                 \
                    _Pragma("unroll")                                                       \
                    for (int jj = 0; jj < 4; jj++)                                          \
                        mma16(acc[i][jj], al[i], &bh[jj >> 1][(jj & 1) * 2]);               \
            }                                                                               \
            {                                                                               \
                u32 bl[2][4];                                                               \
                _Pragma("unroll")                                                           \
                for (int j = 0; j < 2; j++) LDSM4T(bl[j], uBl + kb + j * 32);               \
                _Pragma("unroll")                                                           \
                for (int i = 0; i < 4; i++)                                                 \
                    _Pragma("unroll")                                                       \
                    for (int jj = 0; jj < 4; jj++)                                          \
                        mma16(acc[i][jj], ah[i], &bl[jj >> 1][(jj & 1) * 2]);               \
            }                                                                               \
        }                                                                                   \
        __syncthreads();                                                                    \
    }                                                                                       \
    const int g = lane >> 2, tg = lane & 3;

__global__ __launch_bounds__(256, 2) void gemm_tc(
        const __nv_bfloat16* __restrict__ Ahi, const __nv_bfloat16* __restrict__ Alo,
        const __nv_bfloat16* __restrict__ Bhi, const __nv_bfloat16* __restrict__ Blo,
        float* __restrict__ C, int M, int N, int K) {
    GEMM_MAINLOOP()
#pragma unroll
    for (int i = 0; i < 4; i++)
#pragma unroll
        for (int jj = 0; jj < 4; jj++) {
            const int r0 = bm + wm + i * 16 + g;
            const int c0 = bn + wn + jj * 8 + tg * 2;
            float* p = C + (size_t)r0 * N + c0;
            *(float2*)p = make_float2(acc[i][jj][0], acc[i][jj][1]);
            p += (size_t)8 * N;
            *(float2*)p = make_float2(acc[i][jj][2], acc[i][jj][3]);
        }
}

__global__ __launch_bounds__(256, 2) void gemm_tc_s(
        const __nv_bfloat16* __restrict__ Ahi, const __nv_bfloat16* __restrict__ Alo,
        const __nv_bfloat16* __restrict__ Bhi, const __nv_bfloat16* __restrict__ Blo,
        __nv_bfloat16* __restrict__ Chi, __nv_bfloat16* __restrict__ Clo,
        int M, int N, int K, float scale) {
    GEMM_MAINLOOP()
#pragma unroll
    for (int i = 0; i < 4; i++)
#pragma unroll
        for (int jj = 0; jj < 4; jj++) {
            const int r0 = bm + wm + i * 16 + g;
            const int c0 = bn + wn + jj * 8 + tg * 2;
            size_t off = (size_t)r0 * N + c0;
            u32 lo0, lo1;
            u32 hi0 = split2(acc[i][jj][0] * scale, acc[i][jj][1] * scale, lo0);
            u32 hi1 = split2(acc[i][jj][2] * scale, acc[i][jj][3] * scale, lo1);
            *(u32*)(Chi + off) = hi0;
            *(u32*)(Clo + off) = lo0;
            *(u32*)(Chi + off + (size_t)8 * N) = hi1;
            *(u32*)(Clo + off + (size_t)8 * N) = lo1;
        }
}

// ---------------------------------------------------------------------------
// HMMA flash attention (Q pre-scaled; split hi/lo output written directly).
// ---------------------------------------------------------------------------
#define ATS 136
#define PSTR 72
#define SSTR 68
#define OQH 0
#define OQL 17408
#define OKH 34816
#define OKL 52224
#define OSS 69632
#define OPH 87040
#define OPL 96256
#define OST 105472
#define ATT_SMEM 106240

__global__ __launch_bounds__(256, 2) void mla_attn_tc(
        const __nv_bfloat16* __restrict__ Qhi, const __nv_bfloat16* __restrict__ Qlo,
        const __nv_bfloat16* __restrict__ Khi, const __nv_bfloat16* __restrict__ Klo,
        __nv_bfloat16* __restrict__ Ohi, __nv_bfloat16* __restrict__ Olo) {
    extern __shared__ __align__(16) char sm[];
    const u32 smb = smem_u32(sm);
    float* Sf   = (float*)(sm + OSS);
    float* mrow = (float*)(sm + OST);
    float* lrow = (float*)(sm + OST + 256);
    float* arow = (float*)(sm + OST + 512);

    const int tid = threadIdx.x, lane = tid & 31, wid = tid >> 5;
    const int qb = blockIdx.x, h = blockIdx.y, b = blockIdx.z;
    const int wrow = (wid & 3) * 16;
    const int wn   = (wid >> 2) * 32;
    const int wd   = (wid >> 2) * 64;

    const size_t qoff = ((size_t)b * SS + qb * 64) * DM + h * DH;
    const size_t koff = (size_t)b * SS * DM + h * DH;

#pragma unroll
    for (int s = 0; s < 4; s++) {
        int id = tid + s * 256;
        int r = id >> 4, c = (id & 15) * 8;
        u32 d = (u32)(r * ATS + c) * 2;
        cpa16(smb + OQH + d, Qhi + qoff + (size_t)r * DM + c);
        cpa16(smb + OQL + d, Qlo + qoff + (size_t)r * DM + c);
    }
    CP_COMMIT();
    if (tid < 64) { mrow[tid] = -3.0e38f; lrow[tid] = 0.f; }

    const int lr = (lane & 7) + ((lane >> 3) & 1) * 8;
    const int lc = (lane >> 4) << 3;
    const int g = lane >> 2, tg = lane & 3;

    float of[8][4] = {};

    for (int t = 0; t < SS / 64; t++) {
        __syncthreads();
#pragma unroll
        for (int s = 0; s < 4; s++) {
            int id = tid + s * 256;
            int r = id >> 4, c = (id & 15) * 8;
            u32 d = (u32)(r * ATS + c) * 2;
            const size_t gsrc = koff + (size_t)(t * 64 + r) * DM + c;
            cpa16(smb + OKH + d, Khi + gsrc);
            cpa16(smb + OKL + d, Klo + gsrc);
        }
        CP_COMMIT();
        CP_WAIT0();
        __syncthreads();

        // ---- S = Q @ K^T (3-term split; Q pre-scaled) ----
        float sv[4][4] = {};
#pragma unroll
        for (int kc = 0; kc < 8; kc++) {
            u32 qa = smb + OQH + (u32)((wrow + lr) * ATS + kc * 16 + lc) * 2;
            u32 ah[4], al[4];
            LDSM4(ah, qa);
            LDSM4(al, qa + (OQL - OQH));
#pragma unroll
            for (int nc = 0; nc < 2; nc++) {
                u32 ka = smb + OKH + (u32)((wn + nc * 16 + lr) * ATS + kc * 16 + lc) * 2;
                u32 bh[4], bl[4];
                LDSM4(bh, ka);
                LDSM4(bl, ka + (OKL - OKH));
                u32 f0h[2] = {bh[0], bh[2]}, f1h[2] = {bh[1], bh[3]};
                u32 f0l[2] = {bl[0], bl[2]}, f1l[2] = {bl[1], bl[3]};
                mma16(sv[nc * 2 + 0], ah, f0h);
                mma16(sv[nc * 2 + 1], ah, f1h);
                mma16(sv[nc * 2 + 0], al, f0h);
                mma16(sv[nc * 2 + 1], al, f1h);
                mma16(sv[nc * 2 + 0], ah, f0l);
                mma16(sv[nc * 2 + 1], ah, f1l);
            }
        }
#pragma unroll
        for (int f = 0; f < 4; f++) {
            int col = wn + f * 8 + tg * 2;
            *(float2*)&Sf[(wrow + g) * SSTR + col]     = make_float2(sv[f][0], sv[f][1]);
            *(float2*)&Sf[(wrow + g + 8) * SSTR + col] = make_float2(sv[f][2], sv[f][3]);
        }
        __syncthreads();

        // ---- online softmax (poly exp, split P) ----
        {
            int row = tid >> 2, seg = tid & 3;
            const float* sp = &Sf[row * SSTR + seg * 16];
            float x[16];
            float mloc = -3.0e38f;
#pragma unroll
            for (int c = 0; c < 16; c++) { x[c] = sp[c]; mloc = fmaxf(mloc, x[c]); }
            mloc = fmaxf(mloc, __shfl_xor_sync(0xffffffffu, mloc, 1));
            mloc = fmaxf(mloc, __shfl_xor_sync(0xffffffffu, mloc, 2));
            float mold = mrow[row];
            float mnew = fmaxf(mold, mloc);
            float sloc = 0.f;
            u32* php = (u32*)(sm + OPH) + row * (PSTR / 2) + seg * 8;
            u32* plp = (u32*)(sm + OPL) + row * (PSTR / 2) + seg * 8;
#pragma unroll
            for (int c2 = 0; c2 < 8; c2++) {
                float p0 = fexp(x[2 * c2] - mnew);
                float p1 = fexp(x[2 * c2 + 1] - mnew);
                sloc += p0 + p1;
                u32 lo;
                php[c2] = split2(p0, p1, lo);
                plp[c2] = lo;
            }
            sloc += __shfl_xor_sync(0xffffffffu, sloc, 1);
            sloc += __shfl_xor_sync(0xffffffffu, sloc, 2);
            if (seg == 0) {
                float al = fexp(mold - mnew);
                arow[row] = al;
                mrow[row] = mnew;
                lrow[row] = lrow[row] * al + sloc;
            }
        }
        __syncthreads();

        // ---- O = alpha*O + P @ V (3-term split) ----
        {
            float a0 = arow[wrow + g], a1 = arow[wrow + g + 8];
#pragma unroll
            for (int f = 0; f < 8; f++) {
                of[f][0] *= a0; of[f][1] *= a0;
                of[f][2] *= a1; of[f][3] *= a1;
            }
        }
#pragma unroll
        for (int kc = 0; kc < 4; kc++) {
            u32 pa = smb + OPH + (u32)((wrow + lr) * PSTR + kc * 16 + lc) * 2;
            u32 ah[4], al[4];
            LDSM4(ah, pa);
            LDSM4(al, pa + (OPL - OPH));
#pragma unroll
            for (int ns = 0; ns < 4; ns++) {
                u32 va = smb + OKH + (u32)((kc * 16 + lr) * ATS + wd + ns * 16 + lc) * 2;
                u32 bh[4], bl[4];
                LDSM4T(bh, va);
                LDSM4T(bl, va + (OKL - OKH));
                mma16(of[ns * 2 + 0], ah, &bh[0]);
                mma16(of[ns * 2 + 1], ah, &bh[2]);
                mma16(of[ns * 2 + 0], al, &bh[0]);
                mma16(of[ns * 2 + 1], al, &bh[2]);
                mma16(of[ns * 2 + 0], ah, &bl[0]);
                mma16(of[ns * 2 + 1], ah, &bl[2]);
            }
        }
    }

    // normalize + split-store directly to hi/lo
    float inv0 = 1.f / lrow[wrow + g];
    float inv1 = 1.f / lrow[wrow + g + 8];
    const size_t obase = ((size_t)b * SS + qb * 64 + wrow) * DM + h * DH;
#pragma unroll
    for (int f = 0; f < 8; f++) {
        int col = wd + f * 8 + tg * 2;
        u32 lo0, lo1;
        u32 hi0 = split2(of[f][0] * inv0, of[f][1] * inv0, lo0);
        u32 hi1 = split2(of[f][2] * inv1, of[f][3] * inv1, lo1);
        *(u32*)(Ohi + obase + (size_t)g * DM + col) = hi0;
        *(u32*)(Olo + obase + (size_t)g * DM + col) = lo0;
        *(u32*)(Ohi + obase + (size_t)(g + 8) * DM + col) = hi1;
        *(u32*)(Olo + obase + (size_t)(g + 8) * DM + col) = lo1;
    }
}

// ---------------------------------------------------------------------------
static inline void run_split(const float* src, __nv_bfloat16* hi, __nv_bfloat16* lo, int n) {
    int n4 = n >> 2;
    splitf<<<(n4 + 255) / 256, 256>>>((const float4*)src, (ull*)hi, (ull*)lo, n4);
}

extern "C" void kernel_launch(void* const* d_in, const int* in_sizes, int n_in,
                              void* d_out, int out_size) {
    const float* x    = (const float*)d_in[0];
    const float* W_q  = (const float*)d_in[1];
    const float* W_kd = (const float*)d_in[2];
    const float* W_ku = (const float*)d_in[3];
    const float* W_o  = (const float*)d_in[4];
    float* out = (float*)d_out;

    __nv_bfloat16 *xhi, *xlo, *wqhi, *wqlo, *wkdhi, *wkdlo, *wkuhi, *wkulo;
    __nv_bfloat16 *wohi, *wolo, *lathi, *latlo, *atthi, *attlo;
    __nv_bfloat16 *qhi, *qlo, *kvhi, *kvlo;
    cudaGetSymbolAddress((void**)&xhi,  g_xhi);   cudaGetSymbolAddress((void**)&xlo,  g_xlo);
    cudaGetSymbolAddress((void**)&wqhi, g_wqhi);  cudaGetSymbolAddress((void**)&wqlo, g_wqlo);
    cudaGetSymbolAddress((void**)&wkdhi,g_wkdhi); cudaGetSymbolAddress((void**)&wkdlo,g_wkdlo);
    cudaGetSymbolAddress((void**)&wkuhi,g_wkuhi); cudaGetSymbolAddress((void**)&wkulo,g_wkulo);
    cudaGetSymbolAddress((void**)&wohi, g_wohi);  cudaGetSymbolAddress((void**)&wolo, g_wolo);
    cudaGetSymbolAddress((void**)&lathi,g_lathi); cudaGetSymbolAddress((void**)&latlo,g_latlo);
    cudaGetSymbolAddress((void**)&atthi,g_atthi); cudaGetSymbolAddress((void**)&attlo,g_attlo);
    cudaGetSymbolAddress((void**)&qhi,  g_qhi);   cudaGetSymbolAddress((void**)&qlo,  g_qlo);
    cudaGetSymbolAddress((void**)&kvhi, g_kvhi);  cudaGetSymbolAddress((void**)&kvlo, g_kvlo);

    dim3 blk(256);
    const int gsm = 2 * SBUF;  // 75776
    cudaFuncSetAttribute(gemm_tc,   cudaFuncAttributeMaxDynamicSharedMemorySize, gsm);
    cudaFuncSetAttribute(gemm_tc_s, cudaFuncAttributeMaxDynamicSharedMemorySize, gsm);
    cudaFuncSetAttribute(mla_attn_tc, cudaFuncAttributeMaxDynamicSharedMemorySize, ATT_SMEM);

    // split static operands (inputs only)
    run_split(x,    xhi,  xlo,  ROWS * DM);
    run_split(W_q,  wqhi, wqlo, DM * DM);
    run_split(W_kd, wkdhi, wkdlo, DM * DL);
    run_split(W_ku, wkuhi, wkulo, DL * DM);
    run_split(W_o,  wohi, wolo, DM * DM);

    const float scale = 0.08838834764831843f;  // 1/sqrt(128), folded into q

    // q = (x @ W_q) * scale  -> split output
    gemm_tc_s<<<dim3(DM / 128, ROWS / 128), blk, gsm>>>(xhi, xlo, wqhi, wqlo,
                                                        qhi, qlo, ROWS, DM, DM, scale);
    // latent = x @ W_kv_down -> split output
    gemm_tc_s<<<dim3(DL / 128, ROWS / 128), blk, gsm>>>(xhi, xlo, wkdhi, wkdlo,
                                                        lathi, latlo, ROWS, DL, DM, 1.f);
    // kv = latent @ W_kv_up  -> split output
    gemm_tc_s<<<dim3(DM / 128, ROWS / 128), blk, gsm>>>(lathi, latlo, wkuhi, wkulo,
                                                        kvhi, kvlo, ROWS, DM, DL, 1.f);

    // fused attention (HMMA, writes split hi/lo directly)
    mla_attn_tc<<<dim3(SS / 64, NH, BB), blk, ATT_SMEM>>>(qhi, qlo, kvhi, kvlo, atthi, attlo);

    // out = attn @ W_o (fp32 output)
    gemm_tc<<<dim3(DM / 128, ROWS / 128), blk, gsm>>>(atthi, attlo, wohi, wolo, out, ROWS, DM, DM);
}

// round 15
// speedup vs baseline: 1.0061x; 1.0006x over previous
#include <cuda_runtime.h>
#include <cuda_bf16.h>

#define DM 2048      // d_model
#define NH 16        // heads
#define DH 128       // d_head
#define DL 512       // d_latent
#define BB 2         // batch
#define SS 2048      // seq
#define ROWS (BB * SS)   // 4096

typedef unsigned long long ull;
typedef unsigned int u32;

// ---- scratch: bf16 hi/lo operand copies only (no fp32 intermediates) ----
__device__ __nv_bfloat16 g_xhi[ROWS * DM],  g_xlo[ROWS * DM];
__device__ __nv_bfloat16 g_wqhi[DM * DM],   g_wqlo[DM * DM];
__device__ __nv_bfloat16 g_wkdhi[DM * DL],  g_wkdlo[DM * DL];
__device__ __nv_bfloat16 g_wkuhi[DL * DM],  g_wkulo[DL * DM];
__device__ __nv_bfloat16 g_wohi[DM * DM],   g_wolo[DM * DM];
__device__ __nv_bfloat16 g_lathi[ROWS * DL], g_latlo[ROWS * DL];
__device__ __nv_bfloat16 g_atthi[ROWS * DM], g_attlo[ROWS * DM];
__device__ __nv_bfloat16 g_qhi[ROWS * DM],  g_qlo[ROWS * DM];
__device__ __nv_bfloat16 g_kvhi[ROWS * DM], g_kvlo[ROWS * DM];

// ---- fp32 -> bf16 hi/lo split helpers ----
__device__ __forceinline__ void split4(float4 v, ull& hi, ull& lo) {
    __nv_bfloat16 h0 = __float2bfloat16(v.x), h1 = __float2bfloat16(v.y);
    __nv_bfloat16 h2 = __float2bfloat16(v.z), h3 = __float2bfloat16(v.w);
    __nv_bfloat16 l0 = __float2bfloat16(v.x - __bfloat162float(h0));
    __nv_bfloat16 l1 = __float2bfloat16(v.y - __bfloat162float(h1));
    __nv_bfloat16 l2 = __float2bfloat16(v.z - __bfloat162float(h2));
    __nv_bfloat16 l3 = __float2bfloat16(v.w - __bfloat162float(h3));
    hi = (ull)__bfloat16_as_ushort(h0) | ((ull)__bfloat16_as_ushort(h1) << 16)
       | ((ull)__bfloat16_as_ushort(h2) << 32) | ((ull)__bfloat16_as_ushort(h3) << 48);
    lo = (ull)__bfloat16_as_ushort(l0) | ((ull)__bfloat16_as_ushort(l1) << 16)
       | ((ull)__bfloat16_as_ushort(l2) << 32) | ((ull)__bfloat16_as_ushort(l3) << 48);
}

__device__ __forceinline__ u32 split2(float x, float y, u32& lo) {
    __nv_bfloat162 h = __floats2bfloat162_rn(x, y);
    float lx = x - __bfloat162float(h.x), ly = y - __bfloat162float(h.y);
    __nv_bfloat162 l = __floats2bfloat162_rn(lx, ly);
    lo = *(u32*)&l;
    return *(u32*)&h;
}

__global__ __launch_bounds__(256) void splitf(const float4* __restrict__ src,
                                              ull* __restrict__ hi,
                                              ull* __restrict__ lo, int n4) {
    int i = blockIdx.x * 256 + threadIdx.x;
    if (i < n4) {
        ull h, l; split4(src[i], h, l);
        hi[i] = h; lo[i] = l;
    }
}

// ---- warp MMA plumbing ----
__device__ __forceinline__ u32 smem_u32(const void* p) {
    u32 a; asm("{ .reg .u64 t; cvta.to.shared.u64 t, %1; cvt.u32.u64 %0, t; }" : "=r"(a) : "l"(p)); return a;
}
__device__ __forceinline__ void cpa16(u32 dst, const void* src) {
    asm volatile("cp.async.cg.shared.global [%0], [%1], 16;" :: "r"(dst), "l"(src));
}
#define CP_COMMIT() asm volatile("cp.async.commit_group;" ::: "memory")
#define CP_WAIT1()  asm volatile("cp.async.wait_group 1;" ::: "memory")
#define CP_WAIT0()  asm volatile("cp.async.wait_group 0;" ::: "memory")

#define LDSM4(r, addr) \
    asm volatile("ldmatrix.sync.aligned.m8n8.x4.shared.b16 {%0,%1,%2,%3}, [%4];" \
        : "=r"((r)[0]), "=r"((r)[1]), "=r"((r)[2]), "=r"((r)[3]) : "r"(addr))
#define LDSM4T(r, addr) \
    asm volatile("ldmatrix.sync.aligned.m8n8.x4.trans.shared.b16 {%0,%1,%2,%3}, [%4];" \
        : "=r"((r)[0]), "=r"((r)[1]), "=r"((r)[2]), "=r"((r)[3]) : "r"(addr))

__device__ __forceinline__ void mma16(float* c, const u32* a, const u32* b) {
    asm volatile("mma.sync.aligned.m16n8k16.row.col.f32.bf16.bf16.f32 "
        "{%0,%1,%2,%3}, {%4,%5,%6,%7}, {%8,%9}, {%0,%1,%2,%3};"
        : "+f"(c[0]), "+f"(c[1]), "+f"(c[2]), "+f"(c[3])
        : "r"(a[0]), "r"(a[1]), "r"(a[2]), "r"(a[3]), "r"(b[0]), "r"(b[1]));
}

// fast exp on the FMA pipe (no MUFU): 2^(x*log2e), deg-5 Taylor, err ~2e-6
__device__ __forceinline__ float fexp(float x) {
    x = fmaxf(x, -80.f);
    float y = fmaf(x, 1.44269504f, 12582912.f);
    int ni = __float_as_int(y) - __float_as_int(12582912.f);
    float n = y - 12582912.f;
    float f = fmaf(x, 1.44269504f, -n);
    float p = 0.0013333558f;
    p = fmaf(p, f, 0.0096181291f);
    p = fmaf(p, f, 0.055504109f);
    p = fmaf(p, f, 0.24022651f);
    p = fmaf(p, f, 0.69314718f);
    p = fmaf(p, f, 1.0f);
    return p * __int_as_float((ni + 127) << 23);
}

// ---------------------------------------------------------------------------
// Shared GEMM mainloop (bf16-split 3-term HMMA), two epilogues:
//   gemm_tc   : fp32 C output (final projection)
//   gemm_tc_s : split bf16 hi/lo output (+ optional scale folded in)
// ---------------------------------------------------------------------------
#define ABUF 10240
#define BBUF 8704
#define SBUF 37888

#define GEMM_MAINLOOP()                                                                     \
    extern __shared__ __align__(16) char sm[];                                              \
    const u32 smb = smem_u32(sm);                                                           \
    const int tid = threadIdx.x, lane = tid & 31, wid = tid >> 5;                           \
    const int bm = blockIdx.y << 7, bn = blockIdx.x << 7;                                   \
    const int wm = (wid >> 2) * 64, wn = (wid & 3) * 32;                                    \
    const int sm_m = tid >> 1, sm_kb = (tid & 1) << 4;                                      \
    const int sb_k = tid >> 3, sb_n = (tid & 7) << 4;                                       \
    const size_t gA = (size_t)(bm + sm_m) * K + sm_kb;                                      \
    const size_t gB = (size_t)sb_k * N + bn + sb_n;                                         \
    const u32 dA = (u32)(sm_m * 40 + sm_kb) * 2;                                            \
    const u32 dB = (u32)(sb_k * 136 + sb_n) * 2;                                            \
    const int lrow = (lane & 7) + ((lane >> 3) & 1) * 8;                                    \
    const int lcol = (lane >> 4) << 3;                                                      \
    const u32 a_base = (u32)((wm + lrow) * 40 + lcol) * 2;                                  \
    const u32 b_base = (u32)(lrow * 136 + wn + lcol) * 2;                                   \
    float acc[4][4][4] = {};                                                                \
    const int nCh = K >> 5;                                                                 \
    {                                                                                       \
        const __nv_bfloat16 *pAh = Ahi + gA, *pAl = Alo + gA;                               \
        const __nv_bfloat16 *pBh = Bhi + gB, *pBl = Blo + gB;                               \
        cpa16(smb + dA, pAh);                   cpa16(smb + dA + 16, pAh + 8);              \
        cpa16(smb + ABUF + dA, pAl);            cpa16(smb + ABUF + dA + 16, pAl + 8);       \
        cpa16(smb + 2 * ABUF + dB, pBh);        cpa16(smb + 2 * ABUF + dB + 16, pBh + 8);   \
        cpa16(smb + 2 * ABUF + BBUF + dB, pBl); cpa16(smb + 2 * ABUF + BBUF + dB + 16, pBl + 8); \
        CP_COMMIT();                                                                        \
    }                                                                                       \
    for (int c = 0; c < nCh; c++) {                                                         \
        if (c + 1 < nCh) {                                                                  \
            const u32 o = smb + ((c + 1) & 1) * SBUF;                                       \
            const int kc = (c + 1) << 5;                                                    \
            const __nv_bfloat16 *pAh = Ahi + gA + kc, *pAl = Alo + gA + kc;                 \
            const __nv_bfloat16 *pBh = Bhi + gB + (size_t)kc * N, *pBl = Blo + gB + (size_t)kc * N; \
            cpa16(o + dA, pAh);                   cpa16(o + dA + 16, pAh + 8);              \
            cpa16(o + ABUF + dA, pAl);            cpa16(o + ABUF + dA + 16, pAl + 8);       \
            cpa16(o + 2 * ABUF + dB, pBh);        cpa16(o + 2 * ABUF + dB + 16, pBh + 8);   \
            cpa16(o + 2 * ABUF + BBUF + dB, pBl); cpa16(o + 2 * ABUF + BBUF + dB + 16, pBl + 8); \
            CP_COMMIT();                                                                    \
            CP_WAIT1();                                                                     \
        } else {                                                                            \
            CP_WAIT0();                                                                     \
        }                                                                                   \
        __syncthreads();                                                                    \
        const u32 o = smb + (c & 1) * SBUF;                                                 \
        const u32 uAh = o, uAl = o + ABUF, uBh = o + 2 * ABUF, uBl = o + 2 * ABUF + BBUF;   \
        _Pragma("unroll")                                                                   \
        for (int ks = 0; ks < 2; ks++) {                                                    \
            const u32 ka = a_base + ks * 32;                                                \
            const u32 kb = b_base + ks * 4352;                                              \
            u32 ah[4][4], bh[2][4];                                                         \
            _Pragma("unroll")                                                               \
            for (int i = 0; i < 4; i++) LDSM4(ah[i], uAh + ka + i * 1280);                  \
            _Pragma("unroll")                                                               \
            for (int j = 0; j < 2; j++) LDSM4T(bh[j], uBh + kb + j * 32);                   \
            _Pragma("unroll")                                                               \
            for (int i = 0; i < 4; i++)                                                     \
                _Pragma("unroll")                                                           \
                for (int jj = 0; jj < 4; jj++)                                              \
                    mma16(acc[i][jj], ah[i], &bh[jj >> 1][(jj & 1) * 2]);                   \
            {                                                                               \
                u32 al[4][4];                                                               \
                _Pragma("unroll")                                                           \
                for (int i = 0; i < 4; i++) LDSM4(al[i], uAl + ka + i * 1280);              \
                _Pragma("unroll")                                                           \
                for (int i = 0; i < 4; i++)                                                 \
                    _Pragma("unroll")                                                       \
                    for (int jj = 0; jj < 4; jj++)                                          \
                        mma16(acc[i][jj], al[i], &bh[jj >> 1][(jj & 1) * 2]);               \
            }                                                                               \
            {                                                                               \
                u32 bl[2][4];                                                               \
                _Pragma("unroll")                                                           \
                for (int j = 0; j < 2; j++) LDSM4T(bl[j], uBl + kb + j * 32);               \
                _Pragma("unroll")                                                           \
                for (int i = 0; i < 4; i++)                                                 \
                    _Pragma("unroll")                                                       \
                    for (int jj = 0; jj < 4; jj++)                                          \
                        mma16(acc[i][jj], ah[i], &bl[jj >> 1][(jj & 1) * 2]);               \
            }                                                                               \
        }                                                                                   \
        __syncthreads();                                                                    \
    }                                                                                       \
    const int g = lane >> 2, tg = lane & 3;

__global__ __launch_bounds__(256, 2) void gemm_tc(
        const __nv_bfloat16* __restrict__ Ahi, const __nv_bfloat16* __restrict__ Alo,
        const __nv_bfloat16* __restrict__ Bhi, const __nv_bfloat16* __restrict__ Blo,
        float* __restrict__ C, int M, int N, int K) {
    GEMM_MAINLOOP()
#pragma unroll
    for (int i = 0; i < 4; i++)
#pragma unroll
        for (int jj = 0; jj < 4; jj++) {
            const int r0 = bm + wm + i * 16 + g;
            const int c0 = bn + wn + jj * 8 + tg * 2;
            float* p = C + (size_t)r0 * N + c0;
            *(float2*)p = make_float2(acc[i][jj][0], acc[i][jj][1]);
            p += (size_t)8 * N;
            *(float2*)p = make_float2(acc[i][jj][2], acc[i][jj][3]);
        }
}

__global__ __launch_bounds__(256, 2) void gemm_tc_s(
        const __nv_bfloat16* __restrict__ Ahi, const __nv_bfloat16* __restrict__ Alo,
        const __nv_bfloat16* __restrict__ Bhi, const __nv_bfloat16* __restrict__ Blo,
        __nv_bfloat16* __restrict__ Chi, __nv_bfloat16* __restrict__ Clo,
        int M, int N, int K, float scale) {
    GEMM_MAINLOOP()
#pragma unroll
    for (int i = 0; i < 4; i++)
#pragma unroll
        for (int jj = 0; jj < 4; jj++) {
            const int r0 = bm + wm + i * 16 + g;
            const int c0 = bn + wn + jj * 8 + tg * 2;
            size_t off = (size_t)r0 * N + c0;
            u32 lo0, lo1;
            u32 hi0 = split2(acc[i][jj][0] * scale, acc[i][jj][1] * scale, lo0);
            u32 hi1 = split2(acc[i][jj][2] * scale, acc[i][jj][3] * scale, lo1);
            *(u32*)(Chi + off) = hi0;
            *(u32*)(Clo + off) = lo0;
            *(u32*)(Chi + off + (size_t)8 * N) = hi1;
            *(u32*)(Clo + off + (size_t)8 * N) = lo1;
        }
}

// ---------------------------------------------------------------------------
// HMMA flash attention (Q pre-scaled; split hi/lo output written directly).
// ---------------------------------------------------------------------------
#define ATS 136
#define PSTR 72
#define SSTR 68
#define OQH 0
#define OQL 17408
#define OKH 34816
#define OKL 52224
#define OSS 69632
#define OPH 87040
#define OPL 96256
#define OST 105472
#define ATT_SMEM 106240

__global__ __launch_bounds__(256, 2) void mla_attn_tc(
        const __nv_bfloat16* __restrict__ Qhi, const __nv_bfloat16* __restrict__ Qlo,
        const __nv_bfloat16* __restrict__ Khi, const __nv_bfloat16* __restrict__ Klo,
        __nv_bfloat16* __restrict__ Ohi, __nv_bfloat16* __restrict__ Olo) {
    extern __shared__ __align__(16) char sm[];
    const u32 smb = smem_u32(sm);
    float* Sf   = (float*)(sm + OSS);
    float* mrow = (float*)(sm + OST);
    float* lrow = (float*)(sm + OST + 256);
    float* arow = (float*)(sm + OST + 512);

    const int tid = threadIdx.x, lane = tid & 31, wid = tid >> 5;
    const int qb = blockIdx.x, h = blockIdx.y, b = blockIdx.z;
    const int wrow = (wid & 3) * 16;
    const int wn   = (wid >> 2) * 32;
    const int wd   = (wid >> 2) * 64;

    const size_t qoff = ((size_t)b * SS + qb * 64) * DM + h * DH;
    const size_t koff = (size_t)b * SS * DM + h * DH;

#pragma unroll
    for (int s = 0; s < 4; s++) {
        int id = tid + s * 256;
        int r = id >> 4, c = (id & 15) * 8;
        u32 d = (u32)(r * ATS + c) * 2;
        cpa16(smb + OQH + d, Qhi + qoff + (size_t)r * DM + c);
        cpa16(smb + OQL + d, Qlo + qoff + (size_t)r * DM + c);
    }
    CP_COMMIT();
    if (tid < 64) { mrow[tid] = -3.0e38f; lrow[tid] = 0.f; }

    const int lr = (lane & 7) + ((lane >> 3) & 1) * 8;
    const int lc = (lane >> 4) << 3;
    const int g = lane >> 2, tg = lane & 3;

    float of[8][4] = {};

    for (int t = 0; t < SS / 64; t++) {
        __syncthreads();
#pragma unroll
        for (int s = 0; s < 4; s++) {
            int id = tid + s * 256;
            int r = id >> 4, c = (id & 15) * 8;
            u32 d = (u32)(r * ATS + c) * 2;
            const size_t gsrc = koff + (size_t)(t * 64 + r) * DM + c;
            cpa16(smb + OKH + d, Khi + gsrc);
            cpa16(smb + OKL + d, Klo + gsrc);
        }
        CP_COMMIT();
        CP_WAIT0();
        __syncthreads();

        // ---- S = Q @ K^T (3-term split; Q pre-scaled) ----
        float sv[4][4] = {};
#pragma unroll
        for (int kc = 0; kc < 8; kc++) {
            u32 qa = smb + OQH + (u32)((wrow + lr) * ATS + kc * 16 + lc) * 2;
            u32 ah[4], al[4];
            LDSM4(ah, qa);
            LDSM4(al, qa + (OQL - OQH));
#pragma unroll
            for (int nc = 0; nc < 2; nc++) {
                u32 ka = smb + OKH + (u32)((wn + nc * 16 + lr) * ATS + kc * 16 + lc) * 2;
                u32 bh[4], bl[4];
                LDSM4(bh, ka);
                LDSM4(bl, ka + (OKL - OKH));
                u32 f0h[2] = {bh[0], bh[2]}, f1h[2] = {bh[1], bh[3]};
                u32 f0l[2] = {bl[0], bl[2]}, f1l[2] = {bl[1], bl[3]};
                mma16(sv[nc * 2 + 0], ah, f0h);
                mma16(sv[nc * 2 + 1], ah, f1h);
                mma16(sv[nc * 2 + 0], al, f0h);
                mma16(sv[nc * 2 + 1], al, f1h);
                mma16(sv[nc * 2 + 0], ah, f0l);
                mma16(sv[nc * 2 + 1], ah, f1l);
            }
        }
#pragma unroll
        for (int f = 0; f < 4; f++) {
            int col = wn + f * 8 + tg * 2;
            *(float2*)&Sf[(wrow + g) * SSTR + col]     = make_float2(sv[f][0], sv[f][1]);
            *(float2*)&Sf[(wrow + g + 8) * SSTR + col] = make_float2(sv[f][2], sv[f][3]);
        }
        __syncthreads();

        // ---- online softmax (poly exp, split P) ----
        {
            int row = tid >> 2, seg = tid & 3;
            const float* sp = &Sf[row * SSTR + seg * 16];
            float x[16];
            float mloc = -3.0e38f;
#pragma unroll
            for (int c = 0; c < 16; c++) { x[c] = sp[c]; mloc = fmaxf(mloc, x[c]); }
            mloc = fmaxf(mloc, __shfl_xor_sync(0xffffffffu, mloc, 1));
            mloc = fmaxf(mloc, __shfl_xor_sync(0xffffffffu, mloc, 2));
            float mold = mrow[row];
            float mnew = fmaxf(mold, mloc);
            float sloc = 0.f;
            u32* php = (u32*)(sm + OPH) + row * (PSTR / 2) + seg * 8;
            u32* plp = (u32*)(sm + OPL) + row * (PSTR / 2) + seg * 8;
#pragma unroll
            for (int c2 = 0; c2 < 8; c2++) {
                float p0 = fexp(x[2 * c2] - mnew);
                float p1 = fexp(x[2 * c2 + 1] - mnew);
                sloc += p0 + p1;
                u32 lo;
                php[c2] = split2(p0, p1, lo);
                plp[c2] = lo;
            }
            sloc += __shfl_xor_sync(0xffffffffu, sloc, 1);
            sloc += __shfl_xor_sync(0xffffffffu, sloc, 2);
            if (seg == 0) {
                float al = fexp(mold - mnew);
                arow[row] = al;
                mrow[row] = mnew;
                lrow[row] = lrow[row] * al + sloc;
            }
        }
        __syncthreads();

        // ---- O = alpha*O + P @ V (3-term split) ----
        {
            float a0 = arow[wrow + g], a1 = arow[wrow + g + 8];
#pragma unroll
            for (int f = 0; f < 8; f++) {
                of[f][0] *= a0; of[f][1] *= a0;
                of[f][2] *= a1; of[f][3] *= a1;
            }
        }
#pragma unroll
        for (int kc = 0; kc < 4; kc++) {
            u32 pa = smb + OPH + (u32)((wrow + lr) * PSTR + kc * 16 + lc) * 2;
            u32 ah[4], al[4];
            LDSM4(ah, pa);
            LDSM4(al, pa + (OPL - OPH));
#pragma unroll
            for (int ns = 0; ns < 4; ns++) {
                u32 va = smb + OKH + (u32)((kc * 16 + lr) * ATS + wd + ns * 16 + lc) * 2;
                u32 bh[4], bl[4];
                LDSM4T(bh, va);
                LDSM4T(bl, va + (OKL - OKH));
                mma16(of[ns * 2 + 0], ah, &bh[0]);
                mma16(of[ns * 2 + 1], ah, &bh[2]);
                mma16(of[ns * 2 + 0], al, &bh[0]);
                mma16(of[ns * 2 + 1], al, &bh[2]);
                mma16(of[ns * 2 + 0], ah, &bl[0]);
                mma16(of[ns * 2 + 1], ah, &bl[2]);
            }
        }
    }

    // normalize + split-store directly to hi/lo
    float inv0 = 1.f / lrow[wrow + g];
    float inv1 = 1.f / lrow[wrow + g + 8];
    const size_t obase = ((size_t)b * SS + qb * 64 + wrow) * DM + h * DH;
#pragma unroll
    for (int f = 0; f < 8; f++) {
        int col = wd + f * 8 + tg * 2;
        u32 lo0, lo1;
        u32 hi0 = split2(of[f][0] * inv0, of[f][1] * inv0, lo0);
        u32 hi1 = split2(of[f][2] * inv1, of[f][3] * inv1, lo1);
        *(u32*)(Ohi + obase + (size_t)g * DM + col) = hi0;
        *(u32*)(Olo + obase + (size_t)g * DM + col) = lo0;
        *(u32*)(Ohi + obase + (size_t)(g + 8) * DM + col) = hi1;
        *(u32*)(Olo + obase + (size_t)(g + 8) * DM + col) = lo1;
    }
}

// ---------------------------------------------------------------------------
static inline void run_split(const float* src, __nv_bfloat16* hi, __nv_bfloat16* lo, int n) {
    int n4 = n >> 2;
    splitf<<<(n4 + 255) / 256, 256>>>((const float4*)src, (ull*)hi, (ull*)lo, n4);
}

extern "C" void kernel_launch(void* const* d_in, const int* in_sizes, int n_in,
                              void* d_out, int out_size) {
    const float* x    = (const float*)d_in[0];
    const float* W_q  = (const float*)d_in[1];
    const float* W_kd = (const float*)d_in[2];
    const float* W_ku = (const float*)d_in[3];
    const float* W_o  = (const float*)d_in[4];
    float* out = (float*)d_out;

    __nv_bfloat16 *xhi, *xlo, *wqhi, *wqlo, *wkdhi, *wkdlo, *wkuhi, *wkulo;
    __nv_bfloat16 *wohi, *wolo, *lathi, *latlo, *atthi, *attlo;
    __nv_bfloat16 *qhi, *qlo, *kvhi, *kvlo;
    cudaGetSymbolAddress((void**)&xhi,  g_xhi);   cudaGetSymbolAddress((void**)&xlo,  g_xlo);
    cudaGetSymbolAddress((void**)&wqhi, g_wqhi);  cudaGetSymbolAddress((void**)&wqlo, g_wqlo);
    cudaGetSymbolAddress((void**)&wkdhi,g_wkdhi); cudaGetSymbolAddress((void**)&wkdlo,g_wkdlo);
    cudaGetSymbolAddress((void**)&wkuhi,g_wkuhi); cudaGetSymbolAddress((void**)&wkulo,g_wkulo);
    cudaGetSymbolAddress((void**)&wohi, g_wohi);  cudaGetSymbolAddress((void**)&wolo, g_wolo);
    cudaGetSymbolAddress((void**)&lathi,g_lathi); cudaGetSymbolAddress((void**)&latlo,g_latlo);
    cudaGetSymbolAddress((void**)&atthi,g_atthi); cudaGetSymbolAddress((void**)&attlo,g_attlo);
    cudaGetSymbolAddress((void**)&qhi,  g_qhi);   cudaGetSymbolAddress((void**)&qlo,  g_qlo);
    cudaGetSymbolAddress((void**)&kvhi, g_kvhi);  cudaGetSymbolAddress((void**)&kvlo, g_kvlo);

    dim3 blk(256);
    const int gsm = 2 * SBUF;  // 75776
    cudaFuncSetAttribute(gemm_tc,   cudaFuncAttributeMaxDynamicSharedMemorySize, gsm);
    cudaFuncSetAttribute(gemm_tc_s, cudaFuncAttributeMaxDynamicSharedMemorySize, gsm);
    cudaFuncSetAttribute(mla_attn_tc, cudaFuncAttributeMaxDynamicSharedMemorySize, ATT_SMEM);

    // split static operands (inputs only)
    run_split(x,    xhi,  xlo,  ROWS * DM);
    run_split(W_q,  wqhi, wqlo, DM * DM);
    run_split(W_kd, wkdhi, wkdlo, DM * DL);
    run_split(W_ku, wkuhi, wkulo, DL * DM);
    run_split(W_o,  wohi, wolo, DM * DM);

    const float scale = 0.08838834764831843f;  // 1/sqrt(128), folded into q

    // q = (x @ W_q) * scale  -> split output
    gemm_tc_s<<<dim3(DM / 128, ROWS / 128), blk, gsm>>>(xhi, xlo, wqhi, wqlo,
                                                        qhi, qlo, ROWS, DM, DM, scale);
    // latent = x @ W_kv_down -> split output
    gemm_tc_s<<<dim3(DL / 128, ROWS / 128), blk, gsm>>>(xhi, xlo, wkdhi, wkdlo,
                                                        lathi, latlo, ROWS, DL, DM, 1.f);
    // kv = latent @ W_kv_up  -> split output
    gemm_tc_s<<<dim3(DM / 128, ROWS / 128), blk, gsm>>>(lathi, latlo, wkuhi, wkulo,
                                                        kvhi, kvlo, ROWS, DM, DL, 1.f);

    // fused attention (HMMA, writes split hi/lo directly)
    mla_attn_tc<<<dim3(SS / 64, NH, BB), blk, ATT_SMEM>>>(qhi, qlo, kvhi, kvlo, atthi, attlo);

    // out = attn @ W_o (fp32 output)
    gemm_tc<<<dim3(DM / 128, ROWS / 128), blk, gsm>>>(atthi, attlo, wohi, wolo, out, ROWS, DM, DM);
}

// round 16
// speedup vs baseline: 1.0064x; 1.0004x over previous
#include <cuda_runtime.h>
#include <cuda_bf16.h>

#define DM 2048      // d_model
#define NH 16        // heads
#define DH 128       // d_head
#define DL 512       // d_latent
#define BB 2         // batch
#define SS 2048      // seq
#define ROWS (BB * SS)   // 4096

typedef unsigned long long ull;
typedef unsigned int u32;

// ---- scratch: bf16 hi/lo operand copies only (no fp32 intermediates) ----
__device__ __nv_bfloat16 g_xhi[ROWS * DM],  g_xlo[ROWS * DM];
__device__ __nv_bfloat16 g_wqhi[DM * DM],   g_wqlo[DM * DM];
__device__ __nv_bfloat16 g_wkdhi[DM * DL],  g_wkdlo[DM * DL];
__device__ __nv_bfloat16 g_wkuhi[DL * DM],  g_wkulo[DL * DM];
__device__ __nv_bfloat16 g_wohi[DM * DM],   g_wolo[DM * DM];
__device__ __nv_bfloat16 g_lathi[ROWS * DL], g_latlo[ROWS * DL];
__device__ __nv_bfloat16 g_atthi[ROWS * DM], g_attlo[ROWS * DM];
__device__ __nv_bfloat16 g_qhi[ROWS * DM],  g_qlo[ROWS * DM];
__device__ __nv_bfloat16 g_kvhi[ROWS * DM], g_kvlo[ROWS * DM];

// ---- fp32 -> bf16 hi/lo split helpers ----
__device__ __forceinline__ void split4(float4 v, ull& hi, ull& lo) {
    __nv_bfloat16 h0 = __float2bfloat16(v.x), h1 = __float2bfloat16(v.y);
    __nv_bfloat16 h2 = __float2bfloat16(v.z), h3 = __float2bfloat16(v.w);
    __nv_bfloat16 l0 = __float2bfloat16(v.x - __bfloat162float(h0));
    __nv_bfloat16 l1 = __float2bfloat16(v.y - __bfloat162float(h1));
    __nv_bfloat16 l2 = __float2bfloat16(v.z - __bfloat162float(h2));
    __nv_bfloat16 l3 = __float2bfloat16(v.w - __bfloat162float(h3));
    hi = (ull)__bfloat16_as_ushort(h0) | ((ull)__bfloat16_as_ushort(h1) << 16)
       | ((ull)__bfloat16_as_ushort(h2) << 32) | ((ull)__bfloat16_as_ushort(h3) << 48);
    lo = (ull)__bfloat16_as_ushort(l0) | ((ull)__bfloat16_as_ushort(l1) << 16)
       | ((ull)__bfloat16_as_ushort(l2) << 32) | ((ull)__bfloat16_as_ushort(l3) << 48);
}

__device__ __forceinline__ u32 split2(float x, float y, u32& lo) {
    __nv_bfloat162 h = __floats2bfloat162_rn(x, y);
    float lx = x - __bfloat162float(h.x), ly = y - __bfloat162float(h.y);
    __nv_bfloat162 l = __floats2bfloat162_rn(lx, ly);
    lo = *(u32*)&l;
    return *(u32*)&h;
}

__global__ __launch_bounds__(256) void splitf(const float4* __restrict__ src,
                                              ull* __restrict__ hi,
                                              ull* __restrict__ lo, int n4) {
    int i = blockIdx.x * 256 + threadIdx.x;
    if (i < n4) {
        ull h, l; split4(src[i], h, l);
        hi[i] = h; lo[i] = l;
    }
}

// ---- warp MMA plumbing ----
__device__ __forceinline__ u32 smem_u32(const void* p) {
    u32 a; asm("{ .reg .u64 t; cvta.to.shared.u64 t, %1; cvt.u32.u64 %0, t; }" : "=r"(a) : "l"(p)); return a;
}
__device__ __forceinline__ void cpa16(u32 dst, const void* src) {
    asm volatile("cp.async.cg.shared.global [%0], [%1], 16;" :: "r"(dst), "l"(src));
}
#define CP_COMMIT() asm volatile("cp.async.commit_group;" ::: "memory")
#define CP_WAIT1()  asm volatile("cp.async.wait_group 1;" ::: "memory")
#define CP_WAIT0()  asm volatile("cp.async.wait_group 0;" ::: "memory")

#define LDSM4(r, addr) \
    asm volatile("ldmatrix.sync.aligned.m8n8.x4.shared.b16 {%0,%1,%2,%3}, [%4];" \
        : "=r"((r)[0]), "=r"((r)[1]), "=r"((r)[2]), "=r"((r)[3]) : "r"(addr))
#define LDSM4T(r, addr) \
    asm volatile("ldmatrix.sync.aligned.m8n8.x4.trans.shared.b16 {%0,%1,%2,%3}, [%4];" \
        : "=r"((r)[0]), "=r"((r)[1]), "=r"((r)[2]), "=r"((r)[3]) : "r"(addr))

__device__ __forceinline__ void mma16(float* c, const u32* a, const u32* b) {
    asm volatile("mma.sync.aligned.m16n8k16.row.col.f32.bf16.bf16.f32 "
        "{%0,%1,%2,%3}, {%4,%5,%6,%7}, {%8,%9}, {%0,%1,%2,%3};"
        : "+f"(c[0]), "+f"(c[1]), "+f"(c[2]), "+f"(c[3])
        : "r"(a[0]), "r"(a[1]), "r"(a[2]), "r"(a[3]), "r"(b[0]), "r"(b[1]));
}

// fast exp on the FMA pipe (no MUFU): 2^(x*log2e), deg-5 Taylor, err ~2e-6
__device__ __forceinline__ float fexp(float x) {
    x = fmaxf(x, -80.f);
    float y = fmaf(x, 1.44269504f, 12582912.f);
    int ni = __float_as_int(y) - __float_as_int(12582912.f);
    float n = y - 12582912.f;
    float f = fmaf(x, 1.44269504f, -n);
    float p = 0.0013333558f;
    p = fmaf(p, f, 0.0096181291f);
    p = fmaf(p, f, 0.055504109f);
    p = fmaf(p, f, 0.24022651f);
    p = fmaf(p, f, 0.69314718f);
    p = fmaf(p, f, 1.0f);
    return p * __int_as_float((ni + 127) << 23);
}

// ---------------------------------------------------------------------------
// Shared GEMM mainloop (bf16-split 3-term HMMA), two epilogues:
//   gemm_tc   : fp32 C output (final projection)
//   gemm_tc_s : split bf16 hi/lo output (+ optional scale folded in)
// ---------------------------------------------------------------------------
#define ABUF 10240
#define BBUF 8704
#define SBUF 37888

#define GEMM_MAINLOOP()                                                                     \
    extern __shared__ __align__(16) char sm[];                                              \
    const u32 smb = smem_u32(sm);                                                           \
    const int tid = threadIdx.x, lane = tid & 31, wid = tid >> 5;                           \
    const int bm = blockIdx.y << 7, bn = blockIdx.x << 7;                                   \
    const int wm = (wid >> 2) * 64, wn = (wid & 3) * 32;                                    \
    const int sm_m = tid >> 1, sm_kb = (tid & 1) << 4;                                      \
    const int sb_k = tid >> 3, sb_n = (tid & 7) << 4;                                       \
    const size_t gA = (size_t)(bm + sm_m) * K + sm_kb;                                      \
    const size_t gB = (size_t)sb_k * N + bn + sb_n;                                         \
    const u32 dA = (u32)(sm_m * 40 + sm_kb) * 2;                                            \
    const u32 dB = (u32)(sb_k * 136 + sb_n) * 2;                                            \
    const int lrow = (lane & 7) + ((lane >> 3) & 1) * 8;                                    \
    const int lcol = (lane >> 4) << 3;                                                      \
    const u32 a_base = (u32)((wm + lrow) * 40 + lcol) * 2;                                  \
    const u32 b_base = (u32)(lrow * 136 + wn + lcol) * 2;                                   \
    float acc[4][4][4] = {};                                                                \
    const int nCh = K >> 5;                                                                 \
    {                                                                                       \
        const __nv_bfloat16 *pAh = Ahi + gA, *pAl = Alo + gA;                               \
        const __nv_bfloat16 *pBh = Bhi + gB, *pBl = Blo + gB;                               \
        cpa16(smb + dA, pAh);                   cpa16(smb + dA + 16, pAh + 8);              \
        cpa16(smb + ABUF + dA, pAl);            cpa16(smb + ABUF + dA + 16, pAl + 8);       \
        cpa16(smb + 2 * ABUF + dB, pBh);        cpa16(smb + 2 * ABUF + dB + 16, pBh + 8);   \
        cpa16(smb + 2 * ABUF + BBUF + dB, pBl); cpa16(smb + 2 * ABUF + BBUF + dB + 16, pBl + 8); \
        CP_COMMIT();                                                                        \
    }                                                                                       \
    for (int c = 0; c < nCh; c++) {                                                         \
        if (c + 1 < nCh) {                                                                  \
            const u32 o = smb + ((c + 1) & 1) * SBUF;                                       \
            const int kc = (c + 1) << 5;                                                    \
            const __nv_bfloat16 *pAh = Ahi + gA + kc, *pAl = Alo + gA + kc;                 \
            const __nv_bfloat16 *pBh = Bhi + gB + (size_t)kc * N, *pBl = Blo + gB + (size_t)kc * N; \
            cpa16(o + dA, pAh);                   cpa16(o + dA + 16, pAh + 8);              \
            cpa16(o + ABUF + dA, pAl);            cpa16(o + ABUF + dA + 16, pAl + 8);       \
            cpa16(o + 2 * ABUF + dB, pBh);        cpa16(o + 2 * ABUF + dB + 16, pBh + 8);   \
            cpa16(o + 2 * ABUF + BBUF + dB, pBl); cpa16(o + 2 * ABUF + BBUF + dB + 16, pBl + 8); \
            CP_COMMIT();                                                                    \
            CP_WAIT1();                                                                     \
        } else {                                                                            \
            CP_WAIT0();                                                                     \
        }                                                                                   \
        __syncthreads();                                                                    \
        const u32 o = smb + (c & 1) * SBUF;                                                 \
        const u32 uAh = o, uAl = o + ABUF, uBh = o + 2 * ABUF, uBl = o + 2 * ABUF + BBUF;   \
        _Pragma("unroll")                                                                   \
        for (int ks = 0; ks < 2; ks++) {                                                    \
            const u32 ka = a_base + ks * 32;                                                \
            const u32 kb = b_base + ks * 4352;                                              \
            u32 ah[4][4], bh[2][4];                                                         \
            _Pragma("unroll")                                                               \
            for (int i = 0; i < 4; i++) LDSM4(ah[i], uAh + ka + i * 1280);                  \
            _Pragma("unroll")                                                               \
            for (int j = 0; j < 2; j++) LDSM4T(bh[j], uBh + kb + j * 32);                   \
            _Pragma("unroll")                                                               \
            for (int i = 0; i < 4; i++)                                                     \
                _Pragma("unroll")                                                           \
                for (int jj = 0; jj < 4; jj++)                                              \
                    mma16(acc[i][jj], ah[i], &bh[jj >> 1][(jj & 1) * 2]);                   \
            {                                                                               \
                u32 al[4][4];                                                               \
                _Pragma("unroll")                                                           \
                for (int i = 0; i < 4; i++) LDSM4(al[i], uAl + ka + i * 1280);              \
                _Pragma("unroll")                                                           \
                for (int i = 0; i < 4; i++)                                                 \
                    _Pragma("unroll")                                                       \
                    for (int jj = 0; jj < 4; jj++)                                          \
                        mma16(acc[i][jj], al[i], &bh[jj >> 1][(jj & 1) * 2]);               \
            }                                                                               \
            {                                                                               \
                u32 bl[2][4];                                                               \
                _Pragma("unroll")                                                           \
                for (int j = 0; j < 2; j++) LDSM4T(bl[j], uBl + kb + j * 32);               \
                _Pragma("unroll")                                                           \
                for (int i = 0; i < 4; i++)                                                 \
                    _Pragma("unroll")                                                       \
                    for (int jj = 0; jj < 4; jj++)                                          \
                        mma16(acc[i][jj], ah[i], &bl[jj >> 1][(jj & 1) * 2]);               \
            }                                                                               \
        }                                                                                   \
        __syncthreads();                                                                    \
    }                                                                                       \
    const int g = lane >> 2, tg = lane & 3;

__global__ __launch_bounds__(256, 2) void gemm_tc(
        const __nv_bfloat16* __restrict__ Ahi, const __nv_bfloat16* __restrict__ Alo,
        const __nv_bfloat16* __restrict__ Bhi, const __nv_bfloat16* __restrict__ Blo,
        float* __restrict__ C, int M, int N, int K) {
    GEMM_MAINLOOP()
#pragma unroll
    for (int i = 0; i < 4; i++)
#pragma unroll
        for (int jj = 0; jj < 4; jj++) {
            const int r0 = bm + wm + i * 16 + g;
            const int c0 = bn + wn + jj * 8 + tg * 2;
            float* p = C + (size_t)r0 * N + c0;
            *(float2*)p = make_float2(acc[i][jj][0], acc[i][jj][1]);
            p += (size_t)8 * N;
            *(float2*)p = make_float2(acc[i][jj][2], acc[i][jj][3]);
        }
}

__global__ __launch_bounds__(256, 2) void gemm_tc_s(
        const __nv_bfloat16* __restrict__ Ahi, const __nv_bfloat16* __restrict__ Alo,
        const __nv_bfloat16* __restrict__ Bhi, const __nv_bfloat16* __restrict__ Blo,
        __nv_bfloat16* __restrict__ Chi, __nv_bfloat16* __restrict__ Clo,
        int M, int N, int K, float scale) {
    GEMM_MAINLOOP()
#pragma unroll
    for (int i = 0; i < 4; i++)
#pragma unroll
        for (int jj = 0; jj < 4; jj++) {
            const int r0 = bm + wm + i * 16 + g;
            const int c0 = bn + wn + jj * 8 + tg * 2;
            size_t off = (size_t)r0 * N + c0;
            u32 lo0, lo1;
            u32 hi0 = split2(acc[i][jj][0] * scale, acc[i][jj][1] * scale, lo0);
            u32 hi1 = split2(acc[i][jj][2] * scale, acc[i][jj][3] * scale, lo1);
            *(u32*)(Chi + off) = hi0;
            *(u32*)(Clo + off) = lo0;
            *(u32*)(Chi + off + (size_t)8 * N) = hi1;
            *(u32*)(Clo + off + (size_t)8 * N) = lo1;
        }
}

// ---------------------------------------------------------------------------
// HMMA flash attention (Q pre-scaled; split hi/lo output written directly).
// ---------------------------------------------------------------------------
#define ATS 136
#define PSTR 72
#define SSTR 68
#define OQH 0
#define OQL 17408
#define OKH 34816
#define OKL 52224
#define OSS 69632
#define OPH 87040
#define OPL 96256
#define OST 105472
#define ATT_SMEM 106240

__global__ __launch_bounds__(256, 2) void mla_attn_tc(
        const __nv_bfloat16* __restrict__ Qhi, const __nv_bfloat16* __restrict__ Qlo,
        const __nv_bfloat16* __restrict__ Khi, const __nv_bfloat16* __restrict__ Klo,
        __nv_bfloat16* __restrict__ Ohi, __nv_bfloat16* __restrict__ Olo) {
    extern __shared__ __align__(16) char sm[];
    const u32 smb = smem_u32(sm);
    float* Sf   = (float*)(sm + OSS);
    float* mrow = (float*)(sm + OST);
    float* lrow = (float*)(sm + OST + 256);
    float* arow = (float*)(sm + OST + 512);

    const int tid = threadIdx.x, lane = tid & 31, wid = tid >> 5;
    const int qb = blockIdx.x, h = blockIdx.y, b = blockIdx.z;
    const int wrow = (wid & 3) * 16;
    const int wn   = (wid >> 2) * 32;
    const int wd   = (wid >> 2) * 64;

    const size_t qoff = ((size_t)b * SS + qb * 64) * DM + h * DH;
    const size_t koff = (size_t)b * SS * DM + h * DH;

#pragma unroll
    for (int s = 0; s < 4; s++) {
        int id = tid + s * 256;
        int r = id >> 4, c = (id & 15) * 8;
        u32 d = (u32)(r * ATS + c) * 2;
        cpa16(smb + OQH + d, Qhi + qoff + (size_t)r * DM + c);
        cpa16(smb + OQL + d, Qlo + qoff + (size_t)r * DM + c);
    }
    CP_COMMIT();
    if (tid < 64) { mrow[tid] = -3.0e38f; lrow[tid] = 0.f; }

    const int lr = (lane & 7) + ((lane >> 3) & 1) * 8;
    const int lc = (lane >> 4) << 3;
    const int g = lane >> 2, tg = lane & 3;

    float of[8][4] = {};

    for (int t = 0; t < SS / 64; t++) {
        __syncthreads();
#pragma unroll
        for (int s = 0; s < 4; s++) {
            int id = tid + s * 256;
            int r = id >> 4, c = (id & 15) * 8;
            u32 d = (u32)(r * ATS + c) * 2;
            const size_t gsrc = koff + (size_t)(t * 64 + r) * DM + c;
            cpa16(smb + OKH + d, Khi + gsrc);
            cpa16(smb + OKL + d, Klo + gsrc);
        }
        CP_COMMIT();
        CP_WAIT0();
        __syncthreads();

        // ---- S = Q @ K^T (3-term split; Q pre-scaled) ----
        float sv[4][4] = {};
#pragma unroll
        for (int kc = 0; kc < 8; kc++) {
            u32 qa = smb + OQH + (u32)((wrow + lr) * ATS + kc * 16 + lc) * 2;
            u32 ah[4], al[4];
            LDSM4(ah, qa);
            LDSM4(al, qa + (OQL - OQH));
#pragma unroll
            for (int nc = 0; nc < 2; nc++) {
                u32 ka = smb + OKH + (u32)((wn + nc * 16 + lr) * ATS + kc * 16 + lc) * 2;
                u32 bh[4], bl[4];
                LDSM4(bh, ka);
                LDSM4(bl, ka + (OKL - OKH));
                u32 f0h[2] = {bh[0], bh[2]}, f1h[2] = {bh[1], bh[3]};
                u32 f0l[2] = {bl[0], bl[2]}, f1l[2] = {bl[1], bl[3]};
                mma16(sv[nc * 2 + 0], ah, f0h);
                mma16(sv[nc * 2 + 1], ah, f1h);
                mma16(sv[nc * 2 + 0], al, f0h);
                mma16(sv[nc * 2 + 1], al, f1h);
                mma16(sv[nc * 2 + 0], ah, f0l);
                mma16(sv[nc * 2 + 1], ah, f1l);
            }
        }
#pragma unroll
        for (int f = 0; f < 4; f++) {
            int col = wn + f * 8 + tg * 2;
            *(float2*)&Sf[(wrow + g) * SSTR + col]     = make_float2(sv[f][0], sv[f][1]);
            *(float2*)&Sf[(wrow + g + 8) * SSTR + col] = make_float2(sv[f][2], sv[f][3]);
        }
        __syncthreads();

        // ---- online softmax (poly exp, split P) ----
        {
            int row = tid >> 2, seg = tid & 3;
            const float* sp = &Sf[row * SSTR + seg * 16];
            float x[16];
            float mloc = -3.0e38f;
#pragma unroll
            for (int c = 0; c < 16; c++) { x[c] = sp[c]; mloc = fmaxf(mloc, x[c]); }
            mloc = fmaxf(mloc, __shfl_xor_sync(0xffffffffu, mloc, 1));
            mloc = fmaxf(mloc, __shfl_xor_sync(0xffffffffu, mloc, 2));
            float mold = mrow[row];
            float mnew = fmaxf(mold, mloc);
            float sloc = 0.f;
            u32* php = (u32*)(sm + OPH) + row * (PSTR / 2) + seg * 8;
            u32* plp = (u32*)(sm + OPL) + row * (PSTR / 2) + seg * 8;
#pragma unroll
            for (int c2 = 0; c2 < 8; c2++) {
                float p0 = fexp(x[2 * c2] - mnew);
                float p1 = fexp(x[2 * c2 + 1] - mnew);
                sloc += p0 + p1;
                u32 lo;
                php[c2] = split2(p0, p1, lo);
                plp[c2] = lo;
            }
            sloc += __shfl_xor_sync(0xffffffffu, sloc, 1);
            sloc += __shfl_xor_sync(0xffffffffu, sloc, 2);
            if (seg == 0) {
                float al = fexp(mold - mnew);
                arow[row] = al;
                mrow[row] = mnew;
                lrow[row] = lrow[row] * al + sloc;
            }
        }
        __syncthreads();

        // ---- O = alpha*O + P @ V (3-term split) ----
        {
            float a0 = arow[wrow + g], a1 = arow[wrow + g + 8];
#pragma unroll
            for (int f = 0; f < 8; f++) {
                of[f][0] *= a0; of[f][1] *= a0;
                of[f][2] *= a1; of[f][3] *= a1;
            }
        }
#pragma unroll
        for (int kc = 0; kc < 4; kc++) {
            u32 pa = smb + OPH + (u32)((wrow + lr) * PSTR + kc * 16 + lc) * 2;
            u32 ah[4], al[4];
            LDSM4(ah, pa);
            LDSM4(al, pa + (OPL - OPH));
#pragma unroll
            for (int ns = 0; ns < 4; ns++) {
                u32 va = smb + OKH + (u32)((kc * 16 + lr) * ATS + wd + ns * 16 + lc) * 2;
                u32 bh[4], bl[4];
                LDSM4T(bh, va);
                LDSM4T(bl, va + (OKL - OKH));
                mma16(of[ns * 2 + 0], ah, &bh[0]);
                mma16(of[ns * 2 + 1], ah, &bh[2]);
                mma16(of[ns * 2 + 0], al, &bh[0]);
                mma16(of[ns * 2 + 1], al, &bh[2]);
                mma16(of[ns * 2 + 0], ah, &bl[0]);
                mma16(of[ns * 2 + 1], ah, &bl[2]);
            }
        }
    }

    // normalize + split-store directly to hi/lo
    float inv0 = 1.f / lrow[wrow + g];
    float inv1 = 1.f / lrow[wrow + g + 8];
    const size_t obase = ((size_t)b * SS + qb * 64 + wrow) * DM + h * DH;
#pragma unroll
    for (int f = 0; f < 8; f++) {
        int col = wd + f * 8 + tg * 2;
        u32 lo0, lo1;
        u32 hi0 = split2(of[f][0] * inv0, of[f][1] * inv0, lo0);
        u32 hi1 = split2(of[f][2] * inv1, of[f][3] * inv1, lo1);
        *(u32*)(Ohi + obase + (size_t)g * DM + col) = hi0;
        *(u32*)(Olo + obase + (size_t)g * DM + col) = lo0;
        *(u32*)(Ohi + obase + (size_t)(g + 8) * DM + col) = hi1;
        *(u32*)(Olo + obase + (size_t)(g + 8) * DM + col) = lo1;
    }
}

// ---------------------------------------------------------------------------
static inline void run_split(const float* src, __nv_bfloat16* hi, __nv_bfloat16* lo, int n) {
    int n4 = n >> 2;
    splitf<<<(n4 + 255) / 256, 256>>>((const float4*)src, (ull*)hi, (ull*)lo, n4);
}

extern "C" void kernel_launch(void* const* d_in, const int* in_sizes, int n_in,
                              void* d_out, int out_size) {
    const float* x    = (const float*)d_in[0];
    const float* W_q  = (const float*)d_in[1];
    const float* W_kd = (const float*)d_in[2];
    const float* W_ku = (const float*)d_in[3];
    const float* W_o  = (const float*)d_in[4];
    float* out = (float*)d_out;

    __nv_bfloat16 *xhi, *xlo, *wqhi, *wqlo, *wkdhi, *wkdlo, *wkuhi, *wkulo;
    __nv_bfloat16 *wohi, *wolo, *lathi, *latlo, *atthi, *attlo;
    __nv_bfloat16 *qhi, *qlo, *kvhi, *kvlo;
    cudaGetSymbolAddress((void**)&xhi,  g_xhi);   cudaGetSymbolAddress((void**)&xlo,  g_xlo);
    cudaGetSymbolAddress((void**)&wqhi, g_wqhi);  cudaGetSymbolAddress((void**)&wqlo, g_wqlo);
    cudaGetSymbolAddress((void**)&wkdhi,g_wkdhi); cudaGetSymbolAddress((void**)&wkdlo,g_wkdlo);
    cudaGetSymbolAddress((void**)&wkuhi,g_wkuhi); cudaGetSymbolAddress((void**)&wkulo,g_wkulo);
    cudaGetSymbolAddress((void**)&wohi, g_wohi);  cudaGetSymbolAddress((void**)&wolo, g_wolo);
    cudaGetSymbolAddress((void**)&lathi,g_lathi); cudaGetSymbolAddress((void**)&latlo,g_latlo);
    cudaGetSymbolAddress((void**)&atthi,g_atthi); cudaGetSymbolAddress((void**)&attlo,g_attlo);
    cudaGetSymbolAddress((void**)&qhi,  g_qhi);   cudaGetSymbolAddress((void**)&qlo,  g_qlo);
    cudaGetSymbolAddress((void**)&kvhi, g_kvhi);  cudaGetSymbolAddress((void**)&kvlo, g_kvlo);

    dim3 blk(256);
    const int gsm = 2 * SBUF;  // 75776
    cudaFuncSetAttribute(gemm_tc,   cudaFuncAttributeMaxDynamicSharedMemorySize, gsm);
    cudaFuncSetAttribute(gemm_tc_s, cudaFuncAttributeMaxDynamicSharedMemorySize, gsm);
    cudaFuncSetAttribute(mla_attn_tc, cudaFuncAttributeMaxDynamicSharedMemorySize, ATT_SMEM);

    // split static operands (inputs only)
    run_split(x,    xhi,  xlo,  ROWS * DM);
    run_split(W_q,  wqhi, wqlo, DM * DM);
    run_split(W_kd, wkdhi, wkdlo, DM * DL);
    run_split(W_ku, wkuhi, wkulo, DL * DM);
    run_split(W_o,  wohi, wolo, DM * DM);

    const float scale = 0.08838834764831843f;  // 1/sqrt(128), folded into q

    // q = (x @ W_q) * scale  -> split output
    gemm_tc_s<<<dim3(DM / 128, ROWS / 128), blk, gsm>>>(xhi, xlo, wqhi, wqlo,
                                                        qhi, qlo, ROWS, DM, DM, scale);
    // latent = x @ W_kv_down -> split output
    gemm_tc_s<<<dim3(DL / 128, ROWS / 128), blk, gsm>>>(xhi, xlo, wkdhi, wkdlo,
                                                        lathi, latlo, ROWS, DL, DM, 1.f);
    // kv = latent @ W_kv_up  -> split output
    gemm_tc_s<<<dim3(DM / 128, ROWS / 128), blk, gsm>>>(lathi, latlo, wkuhi, wkulo,
                                                        kvhi, kvlo, ROWS, DM, DL, 1.f);

    // fused attention (HMMA, writes split hi/lo directly)
    mla_attn_tc<<<dim3(SS / 64, NH, BB), blk, ATT_SMEM>>>(qhi, qlo, kvhi, kvlo, atthi, attlo);

    // out = attn @ W_o (fp32 output)
    gemm_tc<<<dim3(DM / 128, ROWS / 128), blk, gsm>>>(atthi, attlo, wohi, wolo, out, ROWS, DM, DM);
}

// round 17
// speedup vs baseline: 1.0077x; 1.0013x over previous
#include <cuda_runtime.h>
#include <cuda_bf16.h>

#define DM 2048      // d_model
#define NH 16        // heads
#define DH 128       // d_head
#define DL 512       // d_latent
#define BB 2         // batch
#define SS 2048      // seq
#define ROWS (BB * SS)   // 4096

typedef unsigned long long ull;
typedef unsigned int u32;

// ---- scratch: bf16 hi/lo operand copies only (no fp32 intermediates) ----
__device__ __nv_bfloat16 g_xhi[ROWS * DM],  g_xlo[ROWS * DM];
__device__ __nv_bfloat16 g_wqhi[DM * DM],   g_wqlo[DM * DM];
__device__ __nv_bfloat16 g_wkdhi[DM * DL],  g_wkdlo[DM * DL];
__device__ __nv_bfloat16 g_wkuhi[DL * DM],  g_wkulo[DL * DM];
__device__ __nv_bfloat16 g_wohi[DM * DM],   g_wolo[DM * DM];
__device__ __nv_bfloat16 g_lathi[ROWS * DL], g_latlo[ROWS * DL];
__device__ __nv_bfloat16 g_atthi[ROWS * DM], g_attlo[ROWS * DM];
__device__ __nv_bfloat16 g_qhi[ROWS * DM],  g_qlo[ROWS * DM];
__device__ __nv_bfloat16 g_kvhi[ROWS * DM], g_kvlo[ROWS * DM];

// ---- fp32 -> bf16 hi/lo split helpers ----
__device__ __forceinline__ void split4(float4 v, ull& hi, ull& lo) {
    __nv_bfloat16 h0 = __float2bfloat16(v.x), h1 = __float2bfloat16(v.y);
    __nv_bfloat16 h2 = __float2bfloat16(v.z), h3 = __float2bfloat16(v.w);
    __nv_bfloat16 l0 = __float2bfloat16(v.x - __bfloat162float(h0));
    __nv_bfloat16 l1 = __float2bfloat16(v.y - __bfloat162float(h1));
    __nv_bfloat16 l2 = __float2bfloat16(v.z - __bfloat162float(h2));
    __nv_bfloat16 l3 = __float2bfloat16(v.w - __bfloat162float(h3));
    hi = (ull)__bfloat16_as_ushort(h0) | ((ull)__bfloat16_as_ushort(h1) << 16)
       | ((ull)__bfloat16_as_ushort(h2) << 32) | ((ull)__bfloat16_as_ushort(h3) << 48);
    lo = (ull)__bfloat16_as_ushort(l0) | ((ull)__bfloat16_as_ushort(l1) << 16)
       | ((ull)__bfloat16_as_ushort(l2) << 32) | ((ull)__bfloat16_as_ushort(l3) << 48);
}

__device__ __forceinline__ u32 split2(float x, float y, u32& lo) {
    __nv_bfloat162 h = __floats2bfloat162_rn(x, y);
    float lx = x - __bfloat162float(h.x), ly = y - __bfloat162float(h.y);
    __nv_bfloat162 l = __floats2bfloat162_rn(lx, ly);
    lo = *(u32*)&l;
    return *(u32*)&h;
}

__global__ __launch_bounds__(256) void splitf(const float4* __restrict__ src,
                                              ull* __restrict__ hi,
                                              ull* __restrict__ lo, int n4) {
    int i = blockIdx.x * 256 + threadIdx.x;
    if (i < n4) {
        ull h, l; split4(src[i], h, l);
        hi[i] = h; lo[i] = l;
    }
}

// ---- warp MMA plumbing ----
__device__ __forceinline__ u32 smem_u32(const void* p) {
    u32 a; asm("{ .reg .u64 t; cvta.to.shared.u64 t, %1; cvt.u32.u64 %0, t; }" : "=r"(a) : "l"(p)); return a;
}
__device__ __forceinline__ void cpa16(u32 dst, const void* src) {
    asm volatile("cp.async.cg.shared.global [%0], [%1], 16;" :: "r"(dst), "l"(src));
}
#define CP_COMMIT() asm volatile("cp.async.commit_group;" ::: "memory")
#define CP_WAIT1()  asm volatile("cp.async.wait_group 1;" ::: "memory")
#define CP_WAIT0()  asm volatile("cp.async.wait_group 0;" ::: "memory")

#define LDSM4(r, addr) \
    asm volatile("ldmatrix.sync.aligned.m8n8.x4.shared.b16 {%0,%1,%2,%3}, [%4];" \
        : "=r"((r)[0]), "=r"((r)[1]), "=r"((r)[2]), "=r"((r)[3]) : "r"(addr))
#define LDSM4T(r, addr) \
    asm volatile("ldmatrix.sync.aligned.m8n8.x4.trans.shared.b16 {%0,%1,%2,%3}, [%4];" \
        : "=r"((r)[0]), "=r"((r)[1]), "=r"((r)[2]), "=r"((r)[3]) : "r"(addr))

__device__ __forceinline__ void mma16(float* c, const u32* a, const u32* b) {
    asm volatile("mma.sync.aligned.m16n8k16.row.col.f32.bf16.bf16.f32 "
        "{%0,%1,%2,%3}, {%4,%5,%6,%7}, {%8,%9}, {%0,%1,%2,%3};"
        : "+f"(c[0]), "+f"(c[1]), "+f"(c[2]), "+f"(c[3])
        : "r"(a[0]), "r"(a[1]), "r"(a[2]), "r"(a[3]), "r"(b[0]), "r"(b[1]));
}

// fast exp on the FMA pipe (no MUFU): 2^(x*log2e), deg-5 Taylor, err ~2e-6
__device__ __forceinline__ float fexp(float x) {
    x = fmaxf(x, -80.f);
    float y = fmaf(x, 1.44269504f, 12582912.f);
    int ni = __float_as_int(y) - __float_as_int(12582912.f);
    float n = y - 12582912.f;
    float f = fmaf(x, 1.44269504f, -n);
    float p = 0.0013333558f;
    p = fmaf(p, f, 0.0096181291f);
    p = fmaf(p, f, 0.055504109f);
    p = fmaf(p, f, 0.24022651f);
    p = fmaf(p, f, 0.69314718f);
    p = fmaf(p, f, 1.0f);
    return p * __int_as_float((ni + 127) << 23);
}

// ---------------------------------------------------------------------------
// Shared GEMM mainloop (bf16-split 3-term HMMA), two epilogues:
//   gemm_tc   : fp32 C output (final projection)
//   gemm_tc_s : split bf16 hi/lo output (+ optional scale folded in)
// ---------------------------------------------------------------------------
#define ABUF 10240
#define BBUF 8704
#define SBUF 37888

#define GEMM_MAINLOOP()                                                                     \
    extern __shared__ __align__(16) char sm[];                                              \
    const u32 smb = smem_u32(sm);                                                           \
    const int tid = threadIdx.x, lane = tid & 31, wid = tid >> 5;                           \
    const int bm = blockIdx.y << 7, bn = blockIdx.x << 7;                                   \
    const int wm = (wid >> 2) * 64, wn = (wid & 3) * 32;                                    \
    const int sm_m = tid >> 1, sm_kb = (tid & 1) << 4;                                      \
    const int sb_k = tid >> 3, sb_n = (tid & 7) << 4;                                       \
    const size_t gA = (size_t)(bm + sm_m) * K + sm_kb;                                      \
    const size_t gB = (size_t)sb_k * N + bn + sb_n;                                         \
    const u32 dA = (u32)(sm_m * 40 + sm_kb) * 2;                                            \
    const u32 dB = (u32)(sb_k * 136 + sb_n) * 2;                                            \
    const int lrow = (lane & 7) + ((lane >> 3) & 1) * 8;                                    \
    const int lcol = (lane >> 4) << 3;                                                      \
    const u32 a_base = (u32)((wm + lrow) * 40 + lcol) * 2;                                  \
    const u32 b_base = (u32)(lrow * 136 + wn + lcol) * 2;                                   \
    float acc[4][4][4] = {};                                                                \
    const int nCh = K >> 5;                                                                 \
    {                                                                                       \
        const __nv_bfloat16 *pAh = Ahi + gA, *pAl = Alo + gA;                               \
        const __nv_bfloat16 *pBh = Bhi + gB, *pBl = Blo + gB;                               \
        cpa16(smb + dA, pAh);                   cpa16(smb + dA + 16, pAh + 8);              \
        cpa16(smb + ABUF + dA, pAl);            cpa16(smb + ABUF + dA + 16, pAl + 8);       \
        cpa16(smb + 2 * ABUF + dB, pBh);        cpa16(smb + 2 * ABUF + dB + 16, pBh + 8);   \
        cpa16(smb + 2 * ABUF + BBUF + dB, pBl); cpa16(smb + 2 * ABUF + BBUF + dB + 16, pBl + 8); \
        CP_COMMIT();                                                                        \
    }                                                                                       \
    for (int c = 0; c < nCh; c++) {                                                         \
        if (c + 1 < nCh) {                                                                  \
            const u32 o = smb + ((c + 1) & 1) * SBUF;                                       \
            const int kc = (c + 1) << 5;                                                    \
            const __nv_bfloat16 *pAh = Ahi + gA + kc, *pAl = Alo + gA + kc;                 \
            const __nv_bfloat16 *pBh = Bhi + gB + (size_t)kc * N, *pBl = Blo + gB + (size_t)kc * N; \
            cpa16(o + dA, pAh);                   cpa16(o + dA + 16, pAh + 8);              \
            cpa16(o + ABUF + dA, pAl);            cpa16(o + ABUF + dA + 16, pAl + 8);       \
            cpa16(o + 2 * ABUF + dB, pBh);        cpa16(o + 2 * ABUF + dB + 16, pBh + 8);   \
            cpa16(o + 2 * ABUF + BBUF + dB, pBl); cpa16(o + 2 * ABUF + BBUF + dB + 16, pBl + 8); \
            CP_COMMIT();                                                                    \
            CP_WAIT1();                                                                     \
        } else {                                                                            \
            CP_WAIT0();                                                                     \
        }                                                                                   \
        __syncthreads();                                                                    \
        const u32 o = smb + (c & 1) * SBUF;                                                 \
        const u32 uAh = o, uAl = o + ABUF, uBh = o + 2 * ABUF, uBl = o + 2 * ABUF + BBUF;   \
        _Pragma("unroll")                                                                   \
        for (int ks = 0; ks < 2; ks++) {                                                    \
            const u32 ka = a_base + ks * 32;                                                \
            const u32 kb = b_base + ks * 4352;                                              \
            u32 ah[4][4], bh[2][4];                                                         \
            _Pragma("unroll")                                                               \
            for (int i = 0; i < 4; i++) LDSM4(ah[i], uAh + ka + i * 1280);                  \
            _Pragma("unroll")                                                               \
            for (int j = 0; j < 2; j++) LDSM4T(bh[j], uBh + kb + j * 32);                   \
            _Pragma("unroll")                                                               \
            for (int i = 0; i < 4; i++)                                                     \
                _Pragma("unroll")                                                           \
                for (int jj = 0; jj < 4; jj++)                                              \
                    mma16(acc[i][jj], ah[i], &bh[jj >> 1][(jj & 1) * 2]);                   \
            {                                                                               \
                u32 al[4][4];                                                               \
                _Pragma("unroll")                                                           \
                for (int i = 0; i < 4; i++) LDSM4(al[i], uAl + ka + i * 1280);              \
                _Pragma("unroll")                                                           \
                for (int i = 0; i < 4; i++)                                                 \
                    _Pragma("unroll")                                                       \
                    for (int jj = 0; jj < 4; jj++)                                          \
                        mma16(acc[i][jj], al[i], &bh[jj >> 1][(jj & 1) * 2]);               \
            }                                                                               \
            {                                                                               \
                u32 bl[2][4];                                                               \
                _Pragma("unroll")                                                           \
                for (int j = 0; j < 2; j++) LDSM4T(bl[j], uBl + kb + j * 32);               \
                _Pragma("unroll")                                                           \
                for (int i = 0; i < 4; i++)                                                 \
                    _Pragma("unroll")                                                       \
                    for (int jj = 0; jj < 4; jj++)                                          \
                        mma16(acc[i][jj], ah[i], &bl[jj >> 1][(jj & 1) * 2]);               \
            }                                                                               \
        }                                                                                   \
        __syncthreads();                                                                    \
    }                                                                                       \
    const int g = lane >> 2, tg = lane & 3;

__global__ __launch_bounds__(256, 2) void gemm_tc(
        const __nv_bfloat16* __restrict__ Ahi, const __nv_bfloat16* __restrict__ Alo,
        const __nv_bfloat16* __restrict__ Bhi, const __nv_bfloat16* __restrict__ Blo,
        float* __restrict__ C, int M, int N, int K) {
    GEMM_MAINLOOP()
#pragma unroll
    for (int i = 0; i < 4; i++)
#pragma unroll
        for (int jj = 0; jj < 4; jj++) {
            const int r0 = bm + wm + i * 16 + g;
            const int c0 = bn + wn + jj * 8 + tg * 2;
            float* p = C + (size_t)r0 * N + c0;
            *(float2*)p = make_float2(acc[i][jj][0], acc[i][jj][1]);
            p += (size_t)8 * N;
            *(float2*)p = make_float2(acc[i][jj][2], acc[i][jj][3]);
        }
}

__global__ __launch_bounds__(256, 2) void gemm_tc_s(
        const __nv_bfloat16* __restrict__ Ahi, const __nv_bfloat16* __restrict__ Alo,
        const __nv_bfloat16* __restrict__ Bhi, const __nv_bfloat16* __restrict__ Blo,
        __nv_bfloat16* __restrict__ Chi, __nv_bfloat16* __restrict__ Clo,
        int M, int N, int K, float scale) {
    GEMM_MAINLOOP()
#pragma unroll
    for (int i = 0; i < 4; i++)
#pragma unroll
        for (int jj = 0; jj < 4; jj++) {
            const int r0 = bm + wm + i * 16 + g;
            const int c0 = bn + wn + jj * 8 + tg * 2;
            size_t off = (size_t)r0 * N + c0;
            u32 lo0, lo1;
            u32 hi0 = split2(acc[i][jj][0] * scale, acc[i][jj][1] * scale, lo0);
            u32 hi1 = split2(acc[i][jj][2] * scale, acc[i][jj][3] * scale, lo1);
            *(u32*)(Chi + off) = hi0;
            *(u32*)(Clo + off) = lo0;
            *(u32*)(Chi + off + (size_t)8 * N) = hi1;
            *(u32*)(Clo + off + (size_t)8 * N) = lo1;
        }
}

// ---------------------------------------------------------------------------
// HMMA flash attention (Q pre-scaled; split hi/lo output written directly).
// ---------------------------------------------------------------------------
#define ATS 136
#define PSTR 72
#define SSTR 68
#define OQH 0
#define OQL 17408
#define OKH 34816
#define OKL 52224
#define OSS 69632
#define OPH 87040
#define OPL 96256
#define OST 105472
#define ATT_SMEM 106240

__global__ __launch_bounds__(256, 2) void mla_attn_tc(
        const __nv_bfloat16* __restrict__ Qhi, const __nv_bfloat16* __restrict__ Qlo,
        const __nv_bfloat16* __restrict__ Khi, const __nv_bfloat16* __restrict__ Klo,
        __nv_bfloat16* __restrict__ Ohi, __nv_bfloat16* __restrict__ Olo) {
    extern __shared__ __align__(16) char sm[];
    const u32 smb = smem_u32(sm);
    float* Sf   = (float*)(sm + OSS);
    float* mrow = (float*)(sm + OST);
    float* lrow = (float*)(sm + OST + 256);
    float* arow = (float*)(sm + OST + 512);

    const int tid = threadIdx.x, lane = tid & 31, wid = tid >> 5;
    const int qb = blockIdx.x, h = blockIdx.y, b = blockIdx.z;
    const int wrow = (wid & 3) * 16;
    const int wn   = (wid >> 2) * 32;
    const int wd   = (wid >> 2) * 64;

    const size_t qoff = ((size_t)b * SS + qb * 64) * DM + h * DH;
    const size_t koff = (size_t)b * SS * DM + h * DH;

#pragma unroll
    for (int s = 0; s < 4; s++) {
        int id = tid + s * 256;
        int r = id >> 4, c = (id & 15) * 8;
        u32 d = (u32)(r * ATS + c) * 2;
        cpa16(smb + OQH + d, Qhi + qoff + (size_t)r * DM + c);
        cpa16(smb + OQL + d, Qlo + qoff + (size_t)r * DM + c);
    }
    CP_COMMIT();
    if (tid < 64) { mrow[tid] = -3.0e38f; lrow[tid] = 0.f; }

    const int lr = (lane & 7) + ((lane >> 3) & 1) * 8;
    const int lc = (lane >> 4) << 3;
    const int g = lane >> 2, tg = lane & 3;

    float of[8][4] = {};

    for (int t = 0; t < SS / 64; t++) {
        __syncthreads();
#pragma unroll
        for (int s = 0; s < 4; s++) {
            int id = tid + s * 256;
            int r = id >> 4, c = (id & 15) * 8;
            u32 d = (u32)(r * ATS + c) * 2;
            const size_t gsrc = koff + (size_t)(t * 64 + r) * DM + c;
            cpa16(smb + OKH + d, Khi + gsrc);
            cpa16(smb + OKL + d, Klo + gsrc);
        }
        CP_COMMIT();
        CP_WAIT0();
        __syncthreads();

        // ---- S = Q @ K^T (3-term split; Q pre-scaled) ----
        float sv[4][4] = {};
#pragma unroll
        for (int kc = 0; kc < 8; kc++) {
            u32 qa = smb + OQH + (u32)((wrow + lr) * ATS + kc * 16 + lc) * 2;
            u32 ah[4], al[4];
            LDSM4(ah, qa);
            LDSM4(al, qa + (OQL - OQH));
#pragma unroll
            for (int nc = 0; nc < 2; nc++) {
                u32 ka = smb + OKH + (u32)((wn + nc * 16 + lr) * ATS + kc * 16 + lc) * 2;
                u32 bh[4], bl[4];
                LDSM4(bh, ka);
                LDSM4(bl, ka + (OKL - OKH));
                u32 f0h[2] = {bh[0], bh[2]}, f1h[2] = {bh[1], bh[3]};
                u32 f0l[2] = {bl[0], bl[2]}, f1l[2] = {bl[1], bl[3]};
                mma16(sv[nc * 2 + 0], ah, f0h);
                mma16(sv[nc * 2 + 1], ah, f1h);
                mma16(sv[nc * 2 + 0], al, f0h);
                mma16(sv[nc * 2 + 1], al, f1h);
                mma16(sv[nc * 2 + 0], ah, f0l);
                mma16(sv[nc * 2 + 1], ah, f1l);
            }
        }
#pragma unroll
        for (int f = 0; f < 4; f++) {
            int col = wn + f * 8 + tg * 2;
            *(float2*)&Sf[(wrow + g) * SSTR + col]     = make_float2(sv[f][0], sv[f][1]);
            *(float2*)&Sf[(wrow + g + 8) * SSTR + col] = make_float2(sv[f][2], sv[f][3]);
        }
        __syncthreads();

        // ---- online softmax (poly exp, split P) ----
        {
            int row = tid >> 2, seg = tid & 3;
            const float* sp = &Sf[row * SSTR + seg * 16];
            float x[16];
            float mloc = -3.0e38f;
#pragma unroll
            for (int c = 0; c < 16; c++) { x[c] = sp[c]; mloc = fmaxf(mloc, x[c]); }
            mloc = fmaxf(mloc, __shfl_xor_sync(0xffffffffu, mloc, 1));
            mloc = fmaxf(mloc, __shfl_xor_sync(0xffffffffu, mloc, 2));
            float mold = mrow[row];
            float mnew = fmaxf(mold, mloc);
            float sloc = 0.f;
            u32* php = (u32*)(sm + OPH) + row * (PSTR / 2) + seg * 8;
            u32* plp = (u32*)(sm + OPL) + row * (PSTR / 2) + seg * 8;
#pragma unroll
            for (int c2 = 0; c2 < 8; c2++) {
                float p0 = fexp(x[2 * c2] - mnew);
                float p1 = fexp(x[2 * c2 + 1] - mnew);
                sloc += p0 + p1;
                u32 lo;
                php[c2] = split2(p0, p1, lo);
                plp[c2] = lo;
            }
            sloc += __shfl_xor_sync(0xffffffffu, sloc, 1);
            sloc += __shfl_xor_sync(0xffffffffu, sloc, 2);
            if (seg == 0) {
                float al = fexp(mold - mnew);
                arow[row] = al;
                mrow[row] = mnew;
                lrow[row] = lrow[row] * al + sloc;
            }
        }
        __syncthreads();

        // ---- O = alpha*O + P @ V (3-term split) ----
        {
            float a0 = arow[wrow + g], a1 = arow[wrow + g + 8];
#pragma unroll
            for (int f = 0; f < 8; f++) {
                of[f][0] *= a0; of[f][1] *= a0;
                of[f][2] *= a1; of[f][3] *= a1;
            }
        }
#pragma unroll
        for (int kc = 0; kc < 4; kc++) {
            u32 pa = smb + OPH + (u32)((wrow + lr) * PSTR + kc * 16 + lc) * 2;
            u32 ah[4], al[4];
            LDSM4(ah, pa);
            LDSM4(al, pa + (OPL - OPH));
#pragma unroll
            for (int ns = 0; ns < 4; ns++) {
                u32 va = smb + OKH + (u32)((kc * 16 + lr) * ATS + wd + ns * 16 + lc) * 2;
                u32 bh[4], bl[4];
                LDSM4T(bh, va);
                LDSM4T(bl, va + (OKL - OKH));
                mma16(of[ns * 2 + 0], ah, &bh[0]);
                mma16(of[ns * 2 + 1], ah, &bh[2]);
                mma16(of[ns * 2 + 0], al, &bh[0]);
                mma16(of[ns * 2 + 1], al, &bh[2]);
                mma16(of[ns * 2 + 0], ah, &bl[0]);
                mma16(of[ns * 2 + 1], ah, &bl[2]);
            }
        }
    }

    // normalize + split-store directly to hi/lo
    float inv0 = 1.f / lrow[wrow + g];
    float inv1 = 1.f / lrow[wrow + g + 8];
    const size_t obase = ((size_t)b * SS + qb * 64 + wrow) * DM + h * DH;
#pragma unroll
    for (int f = 0; f < 8; f++) {
        int col = wd + f * 8 + tg * 2;
        u32 lo0, lo1;
        u32 hi0 = split2(of[f][0] * inv0, of[f][1] * inv0, lo0);
        u32 hi1 = split2(of[f][2] * inv1, of[f][3] * inv1, lo1);
        *(u32*)(Ohi + obase + (size_t)g * DM + col) = hi0;
        *(u32*)(Olo + obase + (size_t)g * DM + col) = lo0;
        *(u32*)(Ohi + obase + (size_t)(g + 8) * DM + col) = hi1;
        *(u32*)(Olo + obase + (size_t)(g + 8) * DM + col) = lo1;
    }
}

// ---------------------------------------------------------------------------
static inline void run_split(const float* src, __nv_bfloat16* hi, __nv_bfloat16* lo, int n) {
    int n4 = n >> 2;
    splitf<<<(n4 + 255) / 256, 256>>>((const float4*)src, (ull*)hi, (ull*)lo, n4);
}

extern "C" void kernel_launch(void* const* d_in, const int* in_sizes, int n_in,
                              void* d_out, int out_size) {
    const float* x    = (const float*)d_in[0];
    const float* W_q  = (const float*)d_in[1];
    const float* W_kd = (const float*)d_in[2];
    const float* W_ku = (const float*)d_in[3];
    const float* W_o  = (const float*)d_in[4];
    float* out = (float*)d_out;

    __nv_bfloat16 *xhi, *xlo, *wqhi, *wqlo, *wkdhi, *wkdlo, *wkuhi, *wkulo;
    __nv_bfloat16 *wohi, *wolo, *lathi, *latlo, *atthi, *attlo;
    __nv_bfloat16 *qhi, *qlo, *kvhi, *kvlo;
    cudaGetSymbolAddress((void**)&xhi,  g_xhi);   cudaGetSymbolAddress((void**)&xlo,  g_xlo);
    cudaGetSymbolAddress((void**)&wqhi, g_wqhi);  cudaGetSymbolAddress((void**)&wqlo, g_wqlo);
    cudaGetSymbolAddress((void**)&wkdhi,g_wkdhi); cudaGetSymbolAddress((void**)&wkdlo,g_wkdlo);
    cudaGetSymbolAddress((void**)&wkuhi,g_wkuhi); cudaGetSymbolAddress((void**)&wkulo,g_wkulo);
    cudaGetSymbolAddress((void**)&wohi, g_wohi);  cudaGetSymbolAddress((void**)&wolo, g_wolo);
    cudaGetSymbolAddress((void**)&lathi,g_lathi); cudaGetSymbolAddress((void**)&latlo,g_latlo);
    cudaGetSymbolAddress((void**)&atthi,g_atthi); cudaGetSymbolAddress((void**)&attlo,g_attlo);
    cudaGetSymbolAddress((void**)&qhi,  g_qhi);   cudaGetSymbolAddress((void**)&qlo,  g_qlo);
    cudaGetSymbolAddress((void**)&kvhi, g_kvhi);  cudaGetSymbolAddress((void**)&kvlo, g_kvlo);

    dim3 blk(256);
    const int gsm = 2 * SBUF;  // 75776
    cudaFuncSetAttribute(gemm_tc,   cudaFuncAttributeMaxDynamicSharedMemorySize, gsm);
    cudaFuncSetAttribute(gemm_tc_s, cudaFuncAttributeMaxDynamicSharedMemorySize, gsm);
    cudaFuncSetAttribute(mla_attn_tc, cudaFuncAttributeMaxDynamicSharedMemorySize, ATT_SMEM);

    // split static operands (inputs only)
    run_split(x,    xhi,  xlo,  ROWS * DM);
    run_split(W_q,  wqhi, wqlo, DM * DM);
    run_split(W_kd, wkdhi, wkdlo, DM * DL);
    run_split(W_ku, wkuhi, wkulo, DL * DM);
    run_split(W_o,  wohi, wolo, DM * DM);

    const float scale = 0.08838834764831843f;  // 1/sqrt(128), folded into q

    // q = (x @ W_q) * scale  -> split output
    gemm_tc_s<<<dim3(DM / 128, ROWS / 128), blk, gsm>>>(xhi, xlo, wqhi, wqlo,
                                                        qhi, qlo, ROWS, DM, DM, scale);
    // latent = x @ W_kv_down -> split output
    gemm_tc_s<<<dim3(DL / 128, ROWS / 128), blk, gsm>>>(xhi, xlo, wkdhi, wkdlo,
                                                        lathi, latlo, ROWS, DL, DM, 1.f);
    // kv = latent @ W_kv_up  -> split output
    gemm_tc_s<<<dim3(DM / 128, ROWS / 128), blk, gsm>>>(lathi, latlo, wkuhi, wkulo,
                                                        kvhi, kvlo, ROWS, DM, DL, 1.f);

    // fused attention (HMMA, writes split hi/lo directly)
    mla_attn_tc<<<dim3(SS / 64, NH, BB), blk, ATT_SMEM>>>(qhi, qlo, kvhi, kvlo, atthi, attlo);

    // out = attn @ W_o (fp32 output)
    gemm_tc<<<dim3(DM / 128, ROWS / 128), blk, gsm>>>(atthi, attlo, wohi, wolo, out, ROWS, DM, DM);
}